// round 12
// baseline (speedup 1.0000x reference)
#include <cuda_runtime.h>
#include <cuda_bf16.h>
#include <cuda_fp16.h>
#include <cstdint>

#define NN 100000
#define EE 300000
#define GG 4000
#define CAP 32

// ---------------- scratch (device globals; no allocation) ----------------
__device__ __align__(16) __half g_a1[NN * 32];            // GEMM1 A: [x_hi(9), x_lo(9), x_hi(9), 0..]
__device__ __align__(16) __half g_w1t[512 * 32];          // GEMM1 B
__device__ __align__(16) __half g_h1h[NN * 512];          // layer1 features fp16 [n][h*128+c]
__device__ __align__(16) float g_as1[NN * 4];
__device__ __align__(16) float g_ad1[NN * 4];
__device__ __align__(16) __half g_o1h[NN * 512];          // layer1 output fp16 (GEMM2 A)
__device__ __align__(16) __half g_w2t[128 * 512];         // W2^T fp16 [n=128][k=512]
__device__ __align__(16) __half g_h2h[NN * 128];          // layer2 projected features fp16
__device__ float g_as2[NN];
__device__ float g_ad2[NN];
__device__ float g_wa[9][8];
__device__ int   g_deg[NN];
__device__ int   g_col[NN * CAP];
__device__ float g_cnt[GG];

__device__ __forceinline__ float lrelu(float x) { return x > 0.f ? x : 0.2f * x; }
__device__ __forceinline__ float eluf(float x)  { return x > 0.f ? x : (__expf(x) - 1.f); }

__device__ __forceinline__ uint32_t smem_to_u32(const void* p) {
    uint32_t a;
    asm("{ .reg .u64 t; cvta.to.shared.u64 t, %1; cvt.u32.u64 %0, t; }" : "=r"(a) : "l"(p));
    return a;
}

#define LDSM_X4(r0, r1, r2, r3, addr) \
    asm volatile("ldmatrix.sync.aligned.m8n8.x4.shared.b16 {%0,%1,%2,%3}, [%4];" \
        : "=r"(r0), "=r"(r1), "=r"(r2), "=r"(r3) : "r"(addr))

__device__ __forceinline__ void mma16816h(float* d, uint32_t a0, uint32_t a1, uint32_t a2,
                                          uint32_t a3, uint32_t b0, uint32_t b1) {
    asm volatile(
        "mma.sync.aligned.m16n8k16.row.col.f32.f16.f16.f32 "
        "{%0,%1,%2,%3}, {%4,%5,%6,%7}, {%8,%9}, {%0,%1,%2,%3};"
        : "+f"(d[0]), "+f"(d[1]), "+f"(d[2]), "+f"(d[3])
        : "r"(a0), "r"(a1), "r"(a2), "r"(a3), "r"(b0), "r"(b1));
}

#define SWZC(rowIdx) (((rowIdx) & 7) << 4)

// ---------------- init: zero out / deg / cnt ----------------
__global__ void k_init(float* __restrict__ out) {
    int i = blockIdx.x * blockDim.x + threadIdx.x;
    if (i < GG * 128) out[i] = 0.f;
    if (i < NN) g_deg[i] = 0;
    if (i < GG) g_cnt[i] = 0.f;
}

// ---------------- merged: weight prep (blocks 0-328) + adjacency fill/cnt (329+) ----------------
__global__ void k_prepfill(const float* __restrict__ W1, const float* __restrict__ W2,
                           const float* __restrict__ a_src1, const float* __restrict__ a_dst1,
                           const int* __restrict__ ei, const int* __restrict__ batch) {
    int b = blockIdx.x;
    if (b < 9) {
        int gw = b * 8 + (threadIdx.x >> 5);
        int lane = threadIdx.x & 31;
        if (gw >= 72) return;
        int k = gw / 8, q = gw % 8, h = q & 3;
        const float* a = (q >= 4) ? a_dst1 : a_src1;
        float s = 0.f;
#pragma unroll
        for (int c = lane; c < 128; c += 32)
            s = fmaf(__ldg(&W1[k * 512 + h * 128 + c]), __ldg(&a[h * 128 + c]), s);
#pragma unroll
        for (int o = 16; o > 0; o >>= 1) s += __shfl_down_sync(0xffffffffu, s, o);
        if (lane == 0) g_wa[k][q] = s;
    } else if (b < 73) {
        int u = (b - 9) * 256 + threadIdx.x;
        int j = u >> 5, k = u & 31;
        __half v = __float2half(0.f);
        if (k < 27) {
            int km = k % 9;
            float w = __ldg(&W1[km * 512 + j]);
            __half hi = __float2half(w);
            v = (k < 18) ? hi : __float2half(w - __half2float(hi));
        }
        g_w1t[u] = v;
    } else if (b < 329) {
        int u = (b - 73) * 256 + threadIdx.x;
        int k = u >> 7, n = u & 127;
        g_w2t[n * 512 + k] = __float2half(__ldg(&W2[u]));
    } else {
        int i = (b - 329) * 256 + threadIdx.x;
        if (i < EE) {
            int s = ei[i], d = ei[EE + i];
            int p = atomicAdd(&g_deg[d], 1);
            if (p < CAP) g_col[d * CAP + p] = s;
        }
        if (i < NN) atomicAdd(&g_cnt[batch[i]], 1.f);
    }
}

// ---------------- GEMM1 A prep + as1/ad1 (thread per node) ----------------
__global__ void k_prep1(const float* __restrict__ x) {
    int n = blockIdx.x * blockDim.x + threadIdx.x;
    if (n >= NN) return;
    float xv[9];
#pragma unroll
    for (int k = 0; k < 9; k++) xv[k] = __ldg(&x[n * 9 + k]);
    __half h16[32];
#pragma unroll
    for (int k = 0; k < 9; k++) {
        __half hi = __float2half(xv[k]);
        h16[k] = hi;
        h16[k + 9] = __float2half(xv[k] - __half2float(hi));
        h16[k + 18] = hi;
    }
#pragma unroll
    for (int k = 27; k < 32; k++) h16[k] = __float2half(0.f);
    uint4* dst = (uint4*)(g_a1 + (size_t)n * 32);
#pragma unroll
    for (int i = 0; i < 4; i++) dst[i] = ((uint4*)h16)[i];
    float s[8];
#pragma unroll
    for (int q = 0; q < 8; q++) {
        float v = 0.f;
#pragma unroll
        for (int k = 0; k < 9; k++) v = fmaf(xv[k], g_wa[k][q], v);
        s[q] = v;
    }
    ((float4*)g_as1)[n] = make_float4(s[0], s[1], s[2], s[3]);
    ((float4*)g_ad1)[n] = make_float4(s[4], s[5], s[6], s[7]);
}

// ---------------- HMMA GEMM1 with swizzle-staged coalesced epilogue ----------------
__global__ __launch_bounds__(256, 2) void k_gemm1_mma() {
    extern __shared__ char smem[];
    char* sA = smem;
    char* sB = smem + 16384;
    uint32_t uA = smem_to_u32(sA);
    uint32_t uB = uA + 16384;

    int tid = threadIdx.x;
    int lane = tid & 31, wid = tid >> 5;
    int warpM = wid & 3, warpN = wid >> 2;
    int rb = warpM * 32, cb = warpN * 64;
    int m0 = blockIdx.x * 128;
    int j0 = blockIdx.y * 128;

    {
        int r = tid & 127;
        bool isA = tid < 128;
        uint4 zero = make_uint4(0, 0, 0, 0);
        const uint4* src;
        bool ok;
        if (isA) {
            int row = m0 + r;
            ok = row < NN;
            src = (const uint4*)(g_a1 + (size_t)(ok ? row : 0) * 32);
        } else {
            ok = true;
            src = (const uint4*)(g_w1t + (size_t)(j0 + r) * 32);
        }
        char* base = isA ? sA : sB;
#pragma unroll
        for (int i = 0; i < 4; i++) {
            uint32_t off = (uint32_t)(r * 128) + (((uint32_t)(i << 4)) ^ SWZC(r));
            *(uint4*)(base + off) = ok ? src[i] : zero;
        }
    }
    __syncthreads();

    float acc[2][8][4];
#pragma unroll
    for (int i = 0; i < 2; i++)
#pragma unroll
        for (int j = 0; j < 8; j++)
#pragma unroll
            for (int q = 0; q < 4; q++) acc[i][j][q] = 0.f;

    int g = lane >> 3;
    int aFr0 = rb + (g & 1) * 8 + (lane & 7);
    uint32_t aKb = (uint32_t)((g >> 1) << 4);
    int bFr0 = cb + (g >> 1) * 8 + (lane & 7);
    uint32_t bKb = (uint32_t)((g & 1) << 4);

#pragma unroll
    for (int kk = 0; kk < 2; kk++) {
        uint32_t kkb = (uint32_t)(kk << 5);
        uint32_t ah[2][4];
#pragma unroll
        for (int mf = 0; mf < 2; mf++) {
            int r = aFr0 + mf * 16;
            uint32_t off = (uint32_t)(r * 128) + ((kkb + aKb) ^ SWZC(r));
            LDSM_X4(ah[mf][0], ah[mf][1], ah[mf][2], ah[mf][3], uA + off);
        }
        uint32_t bh[4][4];
#pragma unroll
        for (int p = 0; p < 4; p++) {
            int r = bFr0 + p * 16;
            uint32_t off = (uint32_t)(r * 128) + ((kkb + bKb) ^ SWZC(r));
            LDSM_X4(bh[p][0], bh[p][1], bh[p][2], bh[p][3], uB + off);
        }
#pragma unroll
        for (int mf = 0; mf < 2; mf++)
#pragma unroll
            for (int p = 0; p < 4; p++) {
                mma16816h(acc[mf][2 * p], ah[mf][0], ah[mf][1], ah[mf][2], ah[mf][3],
                          bh[p][0], bh[p][1]);
                mma16816h(acc[mf][2 * p + 1], ah[mf][0], ah[mf][1], ah[mf][2], ah[mf][3],
                          bh[p][2], bh[p][3]);
            }
    }

    __syncthreads();
    {
        int rq = lane >> 2;
        int cq = (lane & 3) * 2;
#pragma unroll
        for (int nf = 0; nf < 8; nf++) {
            int c = cb + nf * 8 + cq;
#pragma unroll
            for (int mf = 0; mf < 2; mf++) {
                float* a = acc[mf][nf];
                int r0 = rb + mf * 16 + rq;
                int r1 = r0 + 8;
                uint32_t o0 = r0 * 256 + (((uint32_t)(c * 2)) ^ SWZC(r0));
                uint32_t o1 = r1 * 256 + (((uint32_t)(c * 2)) ^ SWZC(r1));
                *(__half2*)(smem + o0) = __floats2half2_rn(a[0], a[1]);
                *(__half2*)(smem + o1) = __floats2half2_rn(a[2], a[3]);
            }
        }
    }
    __syncthreads();
    {
        uint4* gdst = (uint4*)g_h1h;
        int jblk = j0 >> 3;
#pragma unroll
        for (int u = tid; u < 2048; u += 256) {
            int r = u >> 4;
            int blk = u & 15;
            uint32_t src = r * 256 + (((uint32_t)(blk << 4)) ^ SWZC(r));
            int row = m0 + r;
            if (row < NN)
                gdst[(size_t)row * 64 + jblk + blk] = *(const uint4*)(smem + src);
        }
    }
}

// ---------------- layer 1 aggregation: warp per node, depth-1 prefetch ----------------
__global__ __launch_bounds__(256) void k_agg1(const float* __restrict__ b1) {
    int n = blockIdx.x * 8 + (threadIdx.x >> 5);
    if (n >= NN) return;
    int lane = threadIdx.x & 31;
    bool hiHalf = lane >= 16;
    const float4* as4 = (const float4*)g_as1;
    float4 adv = ((const float4*)g_ad1)[n];
    float4 a0 = as4[n];
    float q0 = __expf(lrelu(a0.x + adv.x));
    float q1 = __expf(lrelu(a0.y + adv.y));
    float q2 = __expf(lrelu(a0.z + adv.z));
    float q3 = __expf(lrelu(a0.w + adv.w));
    float z0 = q0, z1 = q1, z2 = q2, z3 = q3;
    float e0 = hiHalf ? q1 : q0;
    float e1 = hiHalf ? q3 : q2;
    float acc[2][8];
    {
        const uint4* hp = (const uint4*)(g_h1h + (size_t)n * 512);
        uint4 qa = hp[lane];
        uint4 qb = hp[lane + 32];
        const __half2* pa = (const __half2*)&qa;
        const __half2* pb = (const __half2*)&qb;
#pragma unroll
        for (int t = 0; t < 4; t++) {
            float2 fa = __half22float2(pa[t]);
            float2 fb = __half22float2(pb[t]);
            acc[0][2 * t] = e0 * fa.x;
            acc[0][2 * t + 1] = e0 * fa.y;
            acc[1][2 * t] = e1 * fb.x;
            acc[1][2 * t + 1] = e1 * fb.y;
        }
    }
    int deg = min(g_deg[n], CAP);
    const int* col = g_col + n * CAP;
    // depth-1 prefetch pipeline
    float4 ac = make_float4(0.f, 0.f, 0.f, 0.f);
    uint4 qac = make_uint4(0, 0, 0, 0), qbc = qac;
    if (deg > 0) {
        int sc = col[0];
        ac = as4[sc];
        const uint4* hp = (const uint4*)(g_h1h + (size_t)sc * 512);
        qac = hp[lane];
        qbc = hp[lane + 32];
    }
    for (int j = 0; j < deg; j++) {
        float4 an = make_float4(0.f, 0.f, 0.f, 0.f);
        uint4 qan = make_uint4(0, 0, 0, 0), qbn = qan;
        if (j + 1 < deg) {
            int sn = col[j + 1];
            an = as4[sn];
            const uint4* hp = (const uint4*)(g_h1h + (size_t)sn * 512);
            qan = hp[lane];
            qbn = hp[lane + 32];
        }
        float p0 = __expf(lrelu(ac.x + adv.x));
        float p1 = __expf(lrelu(ac.y + adv.y));
        float p2 = __expf(lrelu(ac.z + adv.z));
        float p3 = __expf(lrelu(ac.w + adv.w));
        float w0 = hiHalf ? p1 : p0;
        float w1 = hiHalf ? p3 : p2;
        const __half2* pa = (const __half2*)&qac;
        const __half2* pb = (const __half2*)&qbc;
#pragma unroll
        for (int t = 0; t < 4; t++) {
            float2 fa = __half22float2(pa[t]);
            float2 fb = __half22float2(pb[t]);
            acc[0][2 * t] = fmaf(w0, fa.x, acc[0][2 * t]);
            acc[0][2 * t + 1] = fmaf(w0, fa.y, acc[0][2 * t + 1]);
            acc[1][2 * t] = fmaf(w1, fb.x, acc[1][2 * t]);
            acc[1][2 * t + 1] = fmaf(w1, fb.y, acc[1][2 * t + 1]);
        }
        z0 += p0; z1 += p1; z2 += p2; z3 += p3;
        ac = an; qac = qan; qbc = qbn;
    }
    float iz0 = 1.f / (z0 + 1e-16f), iz1 = 1.f / (z1 + 1e-16f);
    float iz2 = 1.f / (z2 + 1e-16f), iz3 = 1.f / (z3 + 1e-16f);
    float izk0 = hiHalf ? iz1 : iz0;
    float izk1 = hiHalf ? iz3 : iz2;
#pragma unroll
    for (int k = 0; k < 2; k++) {
        int u = lane + 32 * k;
        int j0 = u * 8;
        float izk = k == 0 ? izk0 : izk1;
        float4 bv0 = __ldg((const float4*)(b1 + j0));
        float4 bv1 = __ldg((const float4*)(b1 + j0 + 4));
        float v[8];
        v[0] = eluf(acc[k][0] * izk + bv0.x);
        v[1] = eluf(acc[k][1] * izk + bv0.y);
        v[2] = eluf(acc[k][2] * izk + bv0.z);
        v[3] = eluf(acc[k][3] * izk + bv0.w);
        v[4] = eluf(acc[k][4] * izk + bv1.x);
        v[5] = eluf(acc[k][5] * izk + bv1.y);
        v[6] = eluf(acc[k][6] * izk + bv1.z);
        v[7] = eluf(acc[k][7] * izk + bv1.w);
        uint4 pk;
        __half2 h0 = __floats2half2_rn(v[0], v[1]);
        __half2 h1 = __floats2half2_rn(v[2], v[3]);
        __half2 h2 = __floats2half2_rn(v[4], v[5]);
        __half2 h3 = __floats2half2_rn(v[6], v[7]);
        pk.x = *(uint32_t*)&h0; pk.y = *(uint32_t*)&h1;
        pk.z = *(uint32_t*)&h2; pk.w = *(uint32_t*)&h3;
        *(uint4*)(g_o1h + (size_t)n * 512 + j0) = pk;
    }
}

// ---------------- HMMA GEMM2 (sync form), swizzle-staged epilogue + fused alpha2 ----------------
__global__ __launch_bounds__(256, 2) void k_gemm2_mma(const float* __restrict__ a_src2,
                                                      const float* __restrict__ a_dst2) {
    extern __shared__ char smem[];
    char* sA = smem;
    char* sB = smem + 16384;
    uint32_t uA = smem_to_u32(sA);
    uint32_t uB = uA + 16384;

    int tid = threadIdx.x;
    int lane = tid & 31, wid = tid >> 5;
    int warpM = wid & 3, warpN = wid >> 2;
    int rb = warpM * 32, cb = warpN * 64;
    int m0 = blockIdx.x * 128;

    float acc[2][8][4];
#pragma unroll
    for (int i = 0; i < 2; i++)
#pragma unroll
        for (int j = 0; j < 8; j++)
#pragma unroll
            for (int q = 0; q < 4; q++) acc[i][j][q] = 0.f;

    int ldRow = tid >> 1;
    int ldPart = (tid & 1) * 4;
    int aRow = m0 + ldRow;
    bool aOk = aRow < NN;
    uint32_t ldSwc = SWZC(ldRow);
    uint32_t ldRowOff = ldRow * 128;

    int g = lane >> 3;
    int aFr0 = rb + (g & 1) * 8 + (lane & 7);
    uint32_t aKb = (uint32_t)((g >> 1) << 4);
    int bFr0 = cb + (g >> 1) * 8 + (lane & 7);
    uint32_t bKb = (uint32_t)((g & 1) << 4);

    for (int ch = 0; ch < 8; ch++) {
        __syncthreads();
        {
            uint4 zero = make_uint4(0, 0, 0, 0);
            const uint4* pA = (const uint4*)(g_o1h + (size_t)aRow * 512 + ch * 64);
            const uint4* pB = (const uint4*)(g_w2t + (size_t)ldRow * 512 + ch * 64);
#pragma unroll
            for (int i = 0; i < 4; i++) {
                uint32_t kb = (uint32_t)((ldPart + i) << 4);
                uint32_t off = ldRowOff + (kb ^ ldSwc);
                *(uint4*)(sA + off) = aOk ? pA[ldPart + i] : zero;
                *(uint4*)(sB + off) = pB[ldPart + i];
            }
        }
        __syncthreads();
#pragma unroll
        for (int kk = 0; kk < 4; kk++) {
            uint32_t kkb = (uint32_t)(kk << 5);
            uint32_t ah[2][4];
#pragma unroll
            for (int mf = 0; mf < 2; mf++) {
                int r = aFr0 + mf * 16;
                uint32_t off = (uint32_t)(r * 128) + ((kkb + aKb) ^ SWZC(r));
                LDSM_X4(ah[mf][0], ah[mf][1], ah[mf][2], ah[mf][3], uA + off);
            }
            uint32_t bh[4][4];
#pragma unroll
            for (int p = 0; p < 4; p++) {
                int r = bFr0 + p * 16;
                uint32_t off = (uint32_t)(r * 128) + ((kkb + bKb) ^ SWZC(r));
                LDSM_X4(bh[p][0], bh[p][1], bh[p][2], bh[p][3], uB + off);
            }
#pragma unroll
            for (int mf = 0; mf < 2; mf++)
#pragma unroll
                for (int p = 0; p < 4; p++) {
                    mma16816h(acc[mf][2 * p], ah[mf][0], ah[mf][1], ah[mf][2], ah[mf][3],
                              bh[p][0], bh[p][1]);
                    mma16816h(acc[mf][2 * p + 1], ah[mf][0], ah[mf][1], ah[mf][2], ah[mf][3],
                              bh[p][2], bh[p][3]);
                }
        }
    }

    float ps[2][2] = {{0.f, 0.f}, {0.f, 0.f}};
    float pd[2][2] = {{0.f, 0.f}, {0.f, 0.f}};
    int rq = lane >> 2;
    int cq = (lane & 3) * 2;
#pragma unroll
    for (int nf = 0; nf < 8; nf++) {
        int c = cb + nf * 8 + cq;
        float2 sv = __ldg((const float2*)(a_src2 + c));
        float2 dv = __ldg((const float2*)(a_dst2 + c));
#pragma unroll
        for (int mf = 0; mf < 2; mf++) {
            float* a = acc[mf][nf];
            ps[mf][0] = fmaf(a[0], sv.x, fmaf(a[1], sv.y, ps[mf][0]));
            ps[mf][1] = fmaf(a[2], sv.x, fmaf(a[3], sv.y, ps[mf][1]));
            pd[mf][0] = fmaf(a[0], dv.x, fmaf(a[1], dv.y, pd[mf][0]));
            pd[mf][1] = fmaf(a[2], dv.x, fmaf(a[3], dv.y, pd[mf][1]));
        }
    }

    __syncthreads();
#pragma unroll
    for (int nf = 0; nf < 8; nf++) {
        int c = cb + nf * 8 + cq;
#pragma unroll
        for (int mf = 0; mf < 2; mf++) {
            float* a = acc[mf][nf];
            int r0 = rb + mf * 16 + rq;
            int r1 = r0 + 8;
            uint32_t o0 = r0 * 256 + (((uint32_t)(c * 2)) ^ SWZC(r0));
            uint32_t o1 = r1 * 256 + (((uint32_t)(c * 2)) ^ SWZC(r1));
            *(__half2*)(smem + o0) = __floats2half2_rn(a[0], a[1]);
            *(__half2*)(smem + o1) = __floats2half2_rn(a[2], a[3]);
        }
    }
    __syncthreads();
    {
        uint4* gdst = (uint4*)g_h2h;
#pragma unroll
        for (int u = tid; u < 2048; u += 256) {
            int r = u >> 4;
            int blk = u & 15;
            uint32_t src = r * 256 + (((uint32_t)(blk << 4)) ^ SWZC(r));
            int row = m0 + r;
            if (row < NN)
                gdst[(size_t)row * 16 + blk] = *(const uint4*)(smem + src);
        }
    }
    __syncthreads();

    float* red = (float*)smem;
    if (tid < 256) red[tid] = 0.f;
    __syncthreads();
#pragma unroll
    for (int mf = 0; mf < 2; mf++)
#pragma unroll
        for (int h = 0; h < 2; h++) {
#pragma unroll
            for (int o = 1; o <= 2; o <<= 1) {
                ps[mf][h] += __shfl_xor_sync(0xffffffffu, ps[mf][h], o);
                pd[mf][h] += __shfl_xor_sync(0xffffffffu, pd[mf][h], o);
            }
        }
    if ((lane & 3) == 0) {
#pragma unroll
        for (int mf = 0; mf < 2; mf++) {
            int lr = rb + mf * 16 + rq;
            atomicAdd(&red[lr], ps[mf][0]);
            atomicAdd(&red[lr + 8], ps[mf][1]);
            atomicAdd(&red[128 + lr], pd[mf][0]);
            atomicAdd(&red[128 + lr + 8], pd[mf][1]);
        }
    }
    __syncthreads();
    if (tid < 128) {
        int row = m0 + tid;
        if (row < NN) {
            g_as2[row] = red[tid];
            g_ad2[row] = red[128 + tid];
        }
    }
}

// ---------------- layer 2 aggregation, depth-1 prefetch + block-merged pool atomics ----------------
__global__ __launch_bounds__(256) void k_agg2(const float* __restrict__ b2,
                                              const int* __restrict__ batch,
                                              float* __restrict__ out) {
    __shared__ float sval[8][128];
    __shared__ int sg[8];
    int w = threadIdx.x >> 5, lane = threadIdx.x & 31;
    int n = blockIdx.x * 8 + w;
    bool valid = n < NN;
    if (valid) {
        float adn = g_ad2[n];
        float e = __expf(lrelu(g_as2[n] + adn));
        float z = e;
        int deg = min(g_deg[n], CAP);
        const int* col = g_col + n * CAP;
        float a0, a1, a2, a3;
        {
            uint2 q = *(const uint2*)(g_h2h + (size_t)n * 128 + lane * 4);
            float2 f01 = __half22float2(*(__half2*)&q.x);
            float2 f23 = __half22float2(*(__half2*)&q.y);
            a0 = e * f01.x; a1 = e * f01.y; a2 = e * f23.x; a3 = e * f23.y;
        }
        float asc = 0.f;
        uint2 qc = make_uint2(0, 0);
        if (deg > 0) {
            int sc = col[0];
            asc = g_as2[sc];
            qc = *(const uint2*)(g_h2h + (size_t)sc * 128 + lane * 4);
        }
        for (int j = 0; j < deg; j++) {
            float asn = 0.f;
            uint2 qn = make_uint2(0, 0);
            if (j + 1 < deg) {
                int sn = col[j + 1];
                asn = g_as2[sn];
                qn = *(const uint2*)(g_h2h + (size_t)sn * 128 + lane * 4);
            }
            float ee = __expf(lrelu(asc + adn));
            float2 f01 = __half22float2(*(__half2*)&qc.x);
            float2 f23 = __half22float2(*(__half2*)&qc.y);
            a0 = fmaf(ee, f01.x, a0);
            a1 = fmaf(ee, f01.y, a1);
            a2 = fmaf(ee, f23.x, a2);
            a3 = fmaf(ee, f23.y, a3);
            z += ee;
            asc = asn; qc = qn;
        }
        float iz = 1.f / (z + 1e-16f);
        float4 bv = *(const float4*)(b2 + lane * 4);
        sval[w][lane * 4 + 0] = eluf(a0 * iz + bv.x);
        sval[w][lane * 4 + 1] = eluf(a1 * iz + bv.y);
        sval[w][lane * 4 + 2] = eluf(a2 * iz + bv.z);
        sval[w][lane * 4 + 3] = eluf(a3 * iz + bv.w);
        if (lane == 0) sg[w] = batch[n];
    } else if (lane == 0) {
        sg[w] = -1;
    }
    __syncthreads();
    int t = threadIdx.x;
    if (t < 128) {
        float run = 0.f;
        int curg = -1;
#pragma unroll
        for (int w2 = 0; w2 < 8; w2++) {
            int gid = sg[w2];
            if (gid < 0) continue;
            if (gid != curg) {
                if (curg >= 0) atomicAdd(&out[(size_t)curg * 128 + t], run);
                curg = gid;
                run = 0.f;
            }
            run += sval[w2][t];
        }
        if (curg >= 0) atomicAdd(&out[(size_t)curg * 128 + t], run);
    }
}

__global__ void k_pool_div(float* __restrict__ out) {
    int g = blockIdx.x, tid = threadIdx.x;
    out[g * 128 + tid] /= fmaxf(g_cnt[g], 1.f);
}

// ---------------- launcher ----------------
extern "C" void kernel_launch(void* const* d_in, const int* in_sizes, int n_in,
                              void* d_out, int out_size) {
    const float* x       = (const float*)d_in[0];
    const int*   ei      = (const int*)d_in[1];
    const int*   batch   = (const int*)d_in[2];
    const float* W1      = (const float*)d_in[3];
    const float* a_src1  = (const float*)d_in[4];
    const float* a_dst1  = (const float*)d_in[5];
    const float* b1      = (const float*)d_in[6];
    const float* W2      = (const float*)d_in[7];
    const float* a_src2  = (const float*)d_in[8];
    const float* a_dst2  = (const float*)d_in[9];
    const float* b2      = (const float*)d_in[10];
    float* out = (float*)d_out;

    cudaFuncSetAttribute(k_gemm1_mma, cudaFuncAttributeMaxDynamicSharedMemorySize, 32768);
    cudaFuncSetAttribute(k_gemm2_mma, cudaFuncAttributeMaxDynamicSharedMemorySize, 32768);

    k_init<<<(GG * 128 + 255) / 256, 256>>>(out);
    k_prepfill<<<329 + (EE + 255) / 256, 256>>>(W1, W2, a_src1, a_dst1, ei, batch);
    k_prep1<<<(NN + 255) / 256, 256>>>(x);
    {
        dim3 grid((NN + 127) / 128, 4);
        k_gemm1_mma<<<grid, 256, 32768>>>();
    }
    k_agg1<<<(NN + 7) / 8, 256>>>(b1);

    k_gemm2_mma<<<(NN + 127) / 128, 256, 32768>>>(a_src2, a_dst2);

    k_agg2<<<(NN + 7) / 8, 256>>>(b2, batch, out);
    k_pool_div<<<GG, 128>>>(out);
}

// round 13
// speedup vs baseline: 1.0909x; 1.0909x over previous
#include <cuda_runtime.h>
#include <cuda_bf16.h>
#include <cuda_fp16.h>
#include <cstdint>

#define NN 100000
#define EE 300000
#define GG 4000
#define CAP 32

// ---------------- scratch (device globals; no allocation) ----------------
__device__ __align__(16) __half g_a1[NN * 32];            // GEMM1 A: [x_hi(9), x_lo(9), x_hi(9), 0..]
__device__ __align__(16) __half g_w1t[512 * 32];          // GEMM1 B
__device__ __align__(16) __half g_h1h[NN * 512];          // layer1 features fp16 [n][h*128+c]
__device__ __align__(16) float g_as1[NN * 4];
__device__ __align__(16) float g_ad1[NN * 4];
__device__ __align__(16) __half g_o1h[NN * 512];          // layer1 output fp16 (GEMM2 A)
__device__ __align__(16) __half g_w2t[128 * 512];         // W2^T fp16 [n=128][k=512]
__device__ __align__(16) __half g_h2h[NN * 128];          // layer2 projected features fp16
__device__ float g_as2[NN];
__device__ float g_ad2[NN];
__device__ float g_wa[9][8];
__device__ int   g_deg[NN];
__device__ int   g_col[NN * CAP];
__device__ float g_cnt[GG];

__device__ __forceinline__ float lrelu(float x) { return x > 0.f ? x : 0.2f * x; }
__device__ __forceinline__ float eluf(float x)  { return x > 0.f ? x : (__expf(x) - 1.f); }

__device__ __forceinline__ uint32_t smem_to_u32(const void* p) {
    uint32_t a;
    asm("{ .reg .u64 t; cvta.to.shared.u64 t, %1; cvt.u32.u64 %0, t; }" : "=r"(a) : "l"(p));
    return a;
}

#define LDSM_X4(r0, r1, r2, r3, addr) \
    asm volatile("ldmatrix.sync.aligned.m8n8.x4.shared.b16 {%0,%1,%2,%3}, [%4];" \
        : "=r"(r0), "=r"(r1), "=r"(r2), "=r"(r3) : "r"(addr))

__device__ __forceinline__ void mma16816h(float* d, uint32_t a0, uint32_t a1, uint32_t a2,
                                          uint32_t a3, uint32_t b0, uint32_t b1) {
    asm volatile(
        "mma.sync.aligned.m16n8k16.row.col.f32.f16.f16.f32 "
        "{%0,%1,%2,%3}, {%4,%5,%6,%7}, {%8,%9}, {%0,%1,%2,%3};"
        : "+f"(d[0]), "+f"(d[1]), "+f"(d[2]), "+f"(d[3])
        : "r"(a0), "r"(a1), "r"(a2), "r"(a3), "r"(b0), "r"(b1));
}

#define SWZC(rowIdx) (((rowIdx) & 7) << 4)

// ---------------- init: zero out / deg / cnt ----------------
__global__ void k_init(float* __restrict__ out) {
    int i = blockIdx.x * blockDim.x + threadIdx.x;
    if (i < GG * 128) out[i] = 0.f;
    if (i < NN) g_deg[i] = 0;
    if (i < GG) g_cnt[i] = 0.f;
}

// ---------------- merged: weight prep (blocks 0-328) + adjacency fill/cnt (329+) ----------------
__global__ void k_prepfill(const float* __restrict__ W1, const float* __restrict__ W2,
                           const float* __restrict__ a_src1, const float* __restrict__ a_dst1,
                           const int* __restrict__ ei, const int* __restrict__ batch) {
    int b = blockIdx.x;
    if (b < 9) {
        int gw = b * 8 + (threadIdx.x >> 5);
        int lane = threadIdx.x & 31;
        if (gw >= 72) return;
        int k = gw / 8, q = gw % 8, h = q & 3;
        const float* a = (q >= 4) ? a_dst1 : a_src1;
        float s = 0.f;
#pragma unroll
        for (int c = lane; c < 128; c += 32)
            s = fmaf(__ldg(&W1[k * 512 + h * 128 + c]), __ldg(&a[h * 128 + c]), s);
#pragma unroll
        for (int o = 16; o > 0; o >>= 1) s += __shfl_down_sync(0xffffffffu, s, o);
        if (lane == 0) g_wa[k][q] = s;
    } else if (b < 73) {
        int u = (b - 9) * 256 + threadIdx.x;
        int j = u >> 5, k = u & 31;
        __half v = __float2half(0.f);
        if (k < 27) {
            int km = k % 9;
            float w = __ldg(&W1[km * 512 + j]);
            __half hi = __float2half(w);
            v = (k < 18) ? hi : __float2half(w - __half2float(hi));
        }
        g_w1t[u] = v;
    } else if (b < 329) {
        int u = (b - 73) * 256 + threadIdx.x;
        int k = u >> 7, n = u & 127;
        g_w2t[n * 512 + k] = __float2half(__ldg(&W2[u]));
    } else {
        int i = (b - 329) * 256 + threadIdx.x;
        if (i < EE) {
            int s = ei[i], d = ei[EE + i];
            int p = atomicAdd(&g_deg[d], 1);
            if (p < CAP) g_col[d * CAP + p] = s;
        }
        if (i < NN) atomicAdd(&g_cnt[batch[i]], 1.f);
    }
}

// ---------------- GEMM1 A prep + as1/ad1 (thread per node) ----------------
__global__ void k_prep1(const float* __restrict__ x) {
    int n = blockIdx.x * blockDim.x + threadIdx.x;
    if (n >= NN) return;
    float xv[9];
#pragma unroll
    for (int k = 0; k < 9; k++) xv[k] = __ldg(&x[n * 9 + k]);
    __half h16[32];
#pragma unroll
    for (int k = 0; k < 9; k++) {
        __half hi = __float2half(xv[k]);
        h16[k] = hi;
        h16[k + 9] = __float2half(xv[k] - __half2float(hi));
        h16[k + 18] = hi;
    }
#pragma unroll
    for (int k = 27; k < 32; k++) h16[k] = __float2half(0.f);
    uint4* dst = (uint4*)(g_a1 + (size_t)n * 32);
#pragma unroll
    for (int i = 0; i < 4; i++) dst[i] = ((uint4*)h16)[i];
    float s[8];
#pragma unroll
    for (int q = 0; q < 8; q++) {
        float v = 0.f;
#pragma unroll
        for (int k = 0; k < 9; k++) v = fmaf(xv[k], g_wa[k][q], v);
        s[q] = v;
    }
    ((float4*)g_as1)[n] = make_float4(s[0], s[1], s[2], s[3]);
    ((float4*)g_ad1)[n] = make_float4(s[4], s[5], s[6], s[7]);
}

// ---------------- HMMA GEMM1: A-tile resident, loop over 4 j-tiles ----------------
// smem: A [0,16K) persistent; B [16K,32K) per-tile; staging [16K,48K) overlaps B post-MMA.
__global__ __launch_bounds__(256, 2) void k_gemm1_mma() {
    extern __shared__ char smem[];
    char* sA = smem;
    char* sB = smem + 16384;
    char* stage = smem + 16384;
    uint32_t uA = smem_to_u32(sA);
    uint32_t uB = uA + 16384;

    int tid = threadIdx.x;
    int lane = tid & 31, wid = tid >> 5;
    int warpM = wid & 3, warpN = wid >> 2;
    int rb = warpM * 32, cb = warpN * 64;
    int m0 = blockIdx.x * 128;

    uint4 zero = make_uint4(0, 0, 0, 0);

    // load A tile once: 128 rows x 4 uint4 = 512; 2 per thread
    {
#pragma unroll
        for (int it = 0; it < 2; it++) {
            int u = tid + it * 256;
            int r = u >> 2, i = u & 3;
            int row = m0 + r;
            bool ok = row < NN;
            const uint4* src = (const uint4*)(g_a1 + (size_t)(ok ? row : 0) * 32);
            uint32_t off = (uint32_t)(r * 128) + (((uint32_t)(i << 4)) ^ SWZC(r));
            *(uint4*)(sA + off) = ok ? src[i] : zero;
        }
    }

    int g = lane >> 3;
    int aFr0 = rb + (g & 1) * 8 + (lane & 7);
    uint32_t aKb = (uint32_t)((g >> 1) << 4);
    int bFr0 = cb + (g >> 1) * 8 + (lane & 7);
    uint32_t bKb = (uint32_t)((g & 1) << 4);
    int rq = lane >> 2;
    int cq = (lane & 3) * 2;
    uint4* gdst = (uint4*)g_h1h;

    for (int jt = 0; jt < 4; jt++) {
        __syncthreads();   // staging reads of prev iter done; A ready (first iter)
        // load B tile for jt
        {
#pragma unroll
            for (int it = 0; it < 2; it++) {
                int u = tid + it * 256;
                int r = u >> 2, i = u & 3;
                const uint4* src = (const uint4*)(g_w1t + (size_t)(jt * 128 + r) * 32);
                uint32_t off = (uint32_t)(r * 128) + (((uint32_t)(i << 4)) ^ SWZC(r));
                *(uint4*)(sB + off) = src[i];
            }
        }
        __syncthreads();

        float acc[2][8][4];
#pragma unroll
        for (int i = 0; i < 2; i++)
#pragma unroll
            for (int j = 0; j < 8; j++)
#pragma unroll
                for (int q = 0; q < 4; q++) acc[i][j][q] = 0.f;

#pragma unroll
        for (int kk = 0; kk < 2; kk++) {
            uint32_t kkb = (uint32_t)(kk << 5);
            uint32_t ah[2][4];
#pragma unroll
            for (int mf = 0; mf < 2; mf++) {
                int r = aFr0 + mf * 16;
                uint32_t off = (uint32_t)(r * 128) + ((kkb + aKb) ^ SWZC(r));
                LDSM_X4(ah[mf][0], ah[mf][1], ah[mf][2], ah[mf][3], uA + off);
            }
            uint32_t bh[4][4];
#pragma unroll
            for (int p = 0; p < 4; p++) {
                int r = bFr0 + p * 16;
                uint32_t off = (uint32_t)(r * 128) + ((kkb + bKb) ^ SWZC(r));
                LDSM_X4(bh[p][0], bh[p][1], bh[p][2], bh[p][3], uB + off);
            }
#pragma unroll
            for (int mf = 0; mf < 2; mf++)
#pragma unroll
                for (int p = 0; p < 4; p++) {
                    mma16816h(acc[mf][2 * p], ah[mf][0], ah[mf][1], ah[mf][2], ah[mf][3],
                              bh[p][0], bh[p][1]);
                    mma16816h(acc[mf][2 * p + 1], ah[mf][0], ah[mf][1], ah[mf][2], ah[mf][3],
                              bh[p][2], bh[p][3]);
                }
        }
        __syncthreads();   // all warps done reading sB before staging overwrites it

        // staging store (swizzled rows)
#pragma unroll
        for (int nf = 0; nf < 8; nf++) {
            int c = cb + nf * 8 + cq;
#pragma unroll
            for (int mf = 0; mf < 2; mf++) {
                float* a = acc[mf][nf];
                int r0 = rb + mf * 16 + rq;
                int r1 = r0 + 8;
                uint32_t o0 = r0 * 256 + (((uint32_t)(c * 2)) ^ SWZC(r0));
                uint32_t o1 = r1 * 256 + (((uint32_t)(c * 2)) ^ SWZC(r1));
                *(__half2*)(stage + o0) = __floats2half2_rn(a[0], a[1]);
                *(__half2*)(stage + o1) = __floats2half2_rn(a[2], a[3]);
            }
        }
        __syncthreads();

        // coalesced global copy
        {
            int jblk = jt * 16;
#pragma unroll
            for (int u = tid; u < 2048; u += 256) {
                int r = u >> 4;
                int blk = u & 15;
                uint32_t src = r * 256 + (((uint32_t)(blk << 4)) ^ SWZC(r));
                int row = m0 + r;
                if (row < NN)
                    gdst[(size_t)row * 64 + jblk + blk] = *(const uint4*)(stage + src);
            }
        }
    }
}

// ---------------- layer 1 aggregation: warp per node (round-11 form) ----------------
__global__ __launch_bounds__(256) void k_agg1(const float* __restrict__ b1) {
    int n = blockIdx.x * 8 + (threadIdx.x >> 5);
    if (n >= NN) return;
    int lane = threadIdx.x & 31;
    bool hiHalf = lane >= 16;
    const float4* as4 = (const float4*)g_as1;
    float4 adv = ((const float4*)g_ad1)[n];
    float4 a0 = as4[n];
    float q0 = __expf(lrelu(a0.x + adv.x));
    float q1 = __expf(lrelu(a0.y + adv.y));
    float q2 = __expf(lrelu(a0.z + adv.z));
    float q3 = __expf(lrelu(a0.w + adv.w));
    float z0 = q0, z1 = q1, z2 = q2, z3 = q3;
    float e0 = hiHalf ? q1 : q0;
    float e1 = hiHalf ? q3 : q2;
    float acc[2][8];
    {
        const uint4* hp = (const uint4*)(g_h1h + (size_t)n * 512);
        uint4 qa = hp[lane];
        uint4 qb = hp[lane + 32];
        const __half2* pa = (const __half2*)&qa;
        const __half2* pb = (const __half2*)&qb;
#pragma unroll
        for (int t = 0; t < 4; t++) {
            float2 fa = __half22float2(pa[t]);
            float2 fb = __half22float2(pb[t]);
            acc[0][2 * t] = e0 * fa.x;
            acc[0][2 * t + 1] = e0 * fa.y;
            acc[1][2 * t] = e1 * fb.x;
            acc[1][2 * t + 1] = e1 * fb.y;
        }
    }
    int deg = min(g_deg[n], CAP);
    const int* col = g_col + n * CAP;
    for (int j = 0; j < deg; j++) {
        int s = col[j];
        float4 a = as4[s];
        float p0 = __expf(lrelu(a.x + adv.x));
        float p1 = __expf(lrelu(a.y + adv.y));
        float p2 = __expf(lrelu(a.z + adv.z));
        float p3 = __expf(lrelu(a.w + adv.w));
        float w0 = hiHalf ? p1 : p0;
        float w1 = hiHalf ? p3 : p2;
        const uint4* hp = (const uint4*)(g_h1h + (size_t)s * 512);
        uint4 qa = hp[lane];
        uint4 qb = hp[lane + 32];
        const __half2* pa = (const __half2*)&qa;
        const __half2* pb = (const __half2*)&qb;
#pragma unroll
        for (int t = 0; t < 4; t++) {
            float2 fa = __half22float2(pa[t]);
            float2 fb = __half22float2(pb[t]);
            acc[0][2 * t] = fmaf(w0, fa.x, acc[0][2 * t]);
            acc[0][2 * t + 1] = fmaf(w0, fa.y, acc[0][2 * t + 1]);
            acc[1][2 * t] = fmaf(w1, fb.x, acc[1][2 * t]);
            acc[1][2 * t + 1] = fmaf(w1, fb.y, acc[1][2 * t + 1]);
        }
        z0 += p0; z1 += p1; z2 += p2; z3 += p3;
    }
    float iz0 = 1.f / (z0 + 1e-16f), iz1 = 1.f / (z1 + 1e-16f);
    float iz2 = 1.f / (z2 + 1e-16f), iz3 = 1.f / (z3 + 1e-16f);
    float izk0 = hiHalf ? iz1 : iz0;
    float izk1 = hiHalf ? iz3 : iz2;
#pragma unroll
    for (int k = 0; k < 2; k++) {
        int u = lane + 32 * k;
        int j0 = u * 8;
        float izk = k == 0 ? izk0 : izk1;
        float4 bv0 = __ldg((const float4*)(b1 + j0));
        float4 bv1 = __ldg((const float4*)(b1 + j0 + 4));
        float v[8];
        v[0] = eluf(acc[k][0] * izk + bv0.x);
        v[1] = eluf(acc[k][1] * izk + bv0.y);
        v[2] = eluf(acc[k][2] * izk + bv0.z);
        v[3] = eluf(acc[k][3] * izk + bv0.w);
        v[4] = eluf(acc[k][4] * izk + bv1.x);
        v[5] = eluf(acc[k][5] * izk + bv1.y);
        v[6] = eluf(acc[k][6] * izk + bv1.z);
        v[7] = eluf(acc[k][7] * izk + bv1.w);
        uint4 pk;
        __half2 h0 = __floats2half2_rn(v[0], v[1]);
        __half2 h1 = __floats2half2_rn(v[2], v[3]);
        __half2 h2 = __floats2half2_rn(v[4], v[5]);
        __half2 h3 = __floats2half2_rn(v[6], v[7]);
        pk.x = *(uint32_t*)&h0; pk.y = *(uint32_t*)&h1;
        pk.z = *(uint32_t*)&h2; pk.w = *(uint32_t*)&h3;
        *(uint4*)(g_o1h + (size_t)n * 512 + j0) = pk;
    }
}

// ---------------- HMMA GEMM2 (sync form), swizzle-staged epilogue + fused alpha2 ----------------
__global__ __launch_bounds__(256, 2) void k_gemm2_mma(const float* __restrict__ a_src2,
                                                      const float* __restrict__ a_dst2) {
    extern __shared__ char smem[];
    char* sA = smem;
    char* sB = smem + 16384;
    uint32_t uA = smem_to_u32(sA);
    uint32_t uB = uA + 16384;

    int tid = threadIdx.x;
    int lane = tid & 31, wid = tid >> 5;
    int warpM = wid & 3, warpN = wid >> 2;
    int rb = warpM * 32, cb = warpN * 64;
    int m0 = blockIdx.x * 128;

    float acc[2][8][4];
#pragma unroll
    for (int i = 0; i < 2; i++)
#pragma unroll
        for (int j = 0; j < 8; j++)
#pragma unroll
            for (int q = 0; q < 4; q++) acc[i][j][q] = 0.f;

    int ldRow = tid >> 1;
    int ldPart = (tid & 1) * 4;
    int aRow = m0 + ldRow;
    bool aOk = aRow < NN;
    uint32_t ldSwc = SWZC(ldRow);
    uint32_t ldRowOff = ldRow * 128;

    int g = lane >> 3;
    int aFr0 = rb + (g & 1) * 8 + (lane & 7);
    uint32_t aKb = (uint32_t)((g >> 1) << 4);
    int bFr0 = cb + (g >> 1) * 8 + (lane & 7);
    uint32_t bKb = (uint32_t)((g & 1) << 4);

    for (int ch = 0; ch < 8; ch++) {
        __syncthreads();
        {
            uint4 zero = make_uint4(0, 0, 0, 0);
            const uint4* pA = (const uint4*)(g_o1h + (size_t)aRow * 512 + ch * 64);
            const uint4* pB = (const uint4*)(g_w2t + (size_t)ldRow * 512 + ch * 64);
#pragma unroll
            for (int i = 0; i < 4; i++) {
                uint32_t kb = (uint32_t)((ldPart + i) << 4);
                uint32_t off = ldRowOff + (kb ^ ldSwc);
                *(uint4*)(sA + off) = aOk ? pA[ldPart + i] : zero;
                *(uint4*)(sB + off) = pB[ldPart + i];
            }
        }
        __syncthreads();
#pragma unroll
        for (int kk = 0; kk < 4; kk++) {
            uint32_t kkb = (uint32_t)(kk << 5);
            uint32_t ah[2][4];
#pragma unroll
            for (int mf = 0; mf < 2; mf++) {
                int r = aFr0 + mf * 16;
                uint32_t off = (uint32_t)(r * 128) + ((kkb + aKb) ^ SWZC(r));
                LDSM_X4(ah[mf][0], ah[mf][1], ah[mf][2], ah[mf][3], uA + off);
            }
            uint32_t bh[4][4];
#pragma unroll
            for (int p = 0; p < 4; p++) {
                int r = bFr0 + p * 16;
                uint32_t off = (uint32_t)(r * 128) + ((kkb + bKb) ^ SWZC(r));
                LDSM_X4(bh[p][0], bh[p][1], bh[p][2], bh[p][3], uB + off);
            }
#pragma unroll
            for (int mf = 0; mf < 2; mf++)
#pragma unroll
                for (int p = 0; p < 4; p++) {
                    mma16816h(acc[mf][2 * p], ah[mf][0], ah[mf][1], ah[mf][2], ah[mf][3],
                              bh[p][0], bh[p][1]);
                    mma16816h(acc[mf][2 * p + 1], ah[mf][0], ah[mf][1], ah[mf][2], ah[mf][3],
                              bh[p][2], bh[p][3]);
                }
        }
    }

    float ps[2][2] = {{0.f, 0.f}, {0.f, 0.f}};
    float pd[2][2] = {{0.f, 0.f}, {0.f, 0.f}};
    int rq = lane >> 2;
    int cq = (lane & 3) * 2;
#pragma unroll
    for (int nf = 0; nf < 8; nf++) {
        int c = cb + nf * 8 + cq;
        float2 sv = __ldg((const float2*)(a_src2 + c));
        float2 dv = __ldg((const float2*)(a_dst2 + c));
#pragma unroll
        for (int mf = 0; mf < 2; mf++) {
            float* a = acc[mf][nf];
            ps[mf][0] = fmaf(a[0], sv.x, fmaf(a[1], sv.y, ps[mf][0]));
            ps[mf][1] = fmaf(a[2], sv.x, fmaf(a[3], sv.y, ps[mf][1]));
            pd[mf][0] = fmaf(a[0], dv.x, fmaf(a[1], dv.y, pd[mf][0]));
            pd[mf][1] = fmaf(a[2], dv.x, fmaf(a[3], dv.y, pd[mf][1]));
        }
    }

    __syncthreads();
#pragma unroll
    for (int nf = 0; nf < 8; nf++) {
        int c = cb + nf * 8 + cq;
#pragma unroll
        for (int mf = 0; mf < 2; mf++) {
            float* a = acc[mf][nf];
            int r0 = rb + mf * 16 + rq;
            int r1 = r0 + 8;
            uint32_t o0 = r0 * 256 + (((uint32_t)(c * 2)) ^ SWZC(r0));
            uint32_t o1 = r1 * 256 + (((uint32_t)(c * 2)) ^ SWZC(r1));
            *(__half2*)(smem + o0) = __floats2half2_rn(a[0], a[1]);
            *(__half2*)(smem + o1) = __floats2half2_rn(a[2], a[3]);
        }
    }
    __syncthreads();
    {
        uint4* gdst = (uint4*)g_h2h;
#pragma unroll
        for (int u = tid; u < 2048; u += 256) {
            int r = u >> 4;
            int blk = u & 15;
            uint32_t src = r * 256 + (((uint32_t)(blk << 4)) ^ SWZC(r));
            int row = m0 + r;
            if (row < NN)
                gdst[(size_t)row * 16 + blk] = *(const uint4*)(smem + src);
        }
    }
    __syncthreads();

    float* red = (float*)smem;
    if (tid < 256) red[tid] = 0.f;
    __syncthreads();
#pragma unroll
    for (int mf = 0; mf < 2; mf++)
#pragma unroll
        for (int h = 0; h < 2; h++) {
#pragma unroll
            for (int o = 1; o <= 2; o <<= 1) {
                ps[mf][h] += __shfl_xor_sync(0xffffffffu, ps[mf][h], o);
                pd[mf][h] += __shfl_xor_sync(0xffffffffu, pd[mf][h], o);
            }
        }
    if ((lane & 3) == 0) {
#pragma unroll
        for (int mf = 0; mf < 2; mf++) {
            int lr = rb + mf * 16 + rq;
            atomicAdd(&red[lr], ps[mf][0]);
            atomicAdd(&red[lr + 8], ps[mf][1]);
            atomicAdd(&red[128 + lr], pd[mf][0]);
            atomicAdd(&red[128 + lr + 8], pd[mf][1]);
        }
    }
    __syncthreads();
    if (tid < 128) {
        int row = m0 + tid;
        if (row < NN) {
            g_as2[row] = red[tid];
            g_ad2[row] = red[128 + tid];
        }
    }
}

// ---------------- layer 2 aggregation + block-merged pool atomics (round-11 form) ----------------
__global__ __launch_bounds__(256) void k_agg2(const float* __restrict__ b2,
                                              const int* __restrict__ batch,
                                              float* __restrict__ out) {
    __shared__ float sval[8][128];
    __shared__ int sg[8];
    int w = threadIdx.x >> 5, lane = threadIdx.x & 31;
    int n = blockIdx.x * 8 + w;
    bool valid = n < NN;
    if (valid) {
        float adn = g_ad2[n];
        float e = __expf(lrelu(g_as2[n] + adn));
        float z = e;
        int deg = min(g_deg[n], CAP);
        const int* col = g_col + n * CAP;
        float a0, a1, a2, a3;
        {
            uint2 q = *(const uint2*)(g_h2h + (size_t)n * 128 + lane * 4);
            float2 f01 = __half22float2(*(__half2*)&q.x);
            float2 f23 = __half22float2(*(__half2*)&q.y);
            a0 = e * f01.x; a1 = e * f01.y; a2 = e * f23.x; a3 = e * f23.y;
        }
        for (int j = 0; j < deg; j++) {
            int s = col[j];
            float ee = __expf(lrelu(g_as2[s] + adn));
            uint2 q = *(const uint2*)(g_h2h + (size_t)s * 128 + lane * 4);
            float2 f01 = __half22float2(*(__half2*)&q.x);
            float2 f23 = __half22float2(*(__half2*)&q.y);
            a0 = fmaf(ee, f01.x, a0);
            a1 = fmaf(ee, f01.y, a1);
            a2 = fmaf(ee, f23.x, a2);
            a3 = fmaf(ee, f23.y, a3);
            z += ee;
        }
        float iz = 1.f / (z + 1e-16f);
        float4 bv = *(const float4*)(b2 + lane * 4);
        sval[w][lane * 4 + 0] = eluf(a0 * iz + bv.x);
        sval[w][lane * 4 + 1] = eluf(a1 * iz + bv.y);
        sval[w][lane * 4 + 2] = eluf(a2 * iz + bv.z);
        sval[w][lane * 4 + 3] = eluf(a3 * iz + bv.w);
        if (lane == 0) sg[w] = batch[n];
    } else if (lane == 0) {
        sg[w] = -1;
    }
    __syncthreads();
    int t = threadIdx.x;
    if (t < 128) {
        float run = 0.f;
        int curg = -1;
#pragma unroll
        for (int w2 = 0; w2 < 8; w2++) {
            int gid = sg[w2];
            if (gid < 0) continue;
            if (gid != curg) {
                if (curg >= 0) atomicAdd(&out[(size_t)curg * 128 + t], run);
                curg = gid;
                run = 0.f;
            }
            run += sval[w2][t];
        }
        if (curg >= 0) atomicAdd(&out[(size_t)curg * 128 + t], run);
    }
}

__global__ void k_pool_div(float* __restrict__ out) {
    int g = blockIdx.x, tid = threadIdx.x;
    out[g * 128 + tid] /= fmaxf(g_cnt[g], 1.f);
}

// ---------------- launcher ----------------
extern "C" void kernel_launch(void* const* d_in, const int* in_sizes, int n_in,
                              void* d_out, int out_size) {
    const float* x       = (const float*)d_in[0];
    const int*   ei      = (const int*)d_in[1];
    const int*   batch   = (const int*)d_in[2];
    const float* W1      = (const float*)d_in[3];
    const float* a_src1  = (const float*)d_in[4];
    const float* a_dst1  = (const float*)d_in[5];
    const float* b1      = (const float*)d_in[6];
    const float* W2      = (const float*)d_in[7];
    const float* a_src2  = (const float*)d_in[8];
    const float* a_dst2  = (const float*)d_in[9];
    const float* b2      = (const float*)d_in[10];
    float* out = (float*)d_out;

    cudaFuncSetAttribute(k_gemm1_mma, cudaFuncAttributeMaxDynamicSharedMemorySize, 49152);
    cudaFuncSetAttribute(k_gemm2_mma, cudaFuncAttributeMaxDynamicSharedMemorySize, 32768);

    k_init<<<(GG * 128 + 255) / 256, 256>>>(out);
    k_prepfill<<<329 + (EE + 255) / 256, 256>>>(W1, W2, a_src1, a_dst1, ei, batch);
    k_prep1<<<(NN + 255) / 256, 256>>>(x);
    k_gemm1_mma<<<(NN + 127) / 128, 256, 49152>>>();
    k_agg1<<<(NN + 7) / 8, 256>>>(b1);

    k_gemm2_mma<<<(NN + 127) / 128, 256, 32768>>>(a_src2, a_dst2);

    k_agg2<<<(NN + 7) / 8, 256>>>(b2, batch, out);
    k_pool_div<<<GG, 128>>>(out);
}

// round 14
// speedup vs baseline: 1.2587x; 1.1539x over previous
#include <cuda_runtime.h>
#include <cuda_bf16.h>
#include <cuda_fp16.h>
#include <cstdint>

#define NN 100000
#define EE 300000
#define GG 4000
#define CAP 32

// ---------------- scratch (device globals; no allocation) ----------------
__device__ __align__(16) __half g_w1t[512 * 32];          // GEMM1 B: [j][W_hi(9),W_hi(9),W_lo(9),0..]
__device__ __align__(16) __half g_ax[NN * 128];           // aggregated x, per head: [n][h*32+k] packed hi/lo/hi
__device__ __align__(16) float g_as1[NN * 4];
__device__ __align__(16) float g_ad1[NN * 4];
__device__ __align__(16) __half g_o1h[NN * 512];          // layer1 output fp16 (GEMM2 A)
__device__ __align__(16) __half g_w2t[128 * 512];         // W2^T fp16 [n=128][k=512]
__device__ __align__(16) __half g_h2h[NN * 128];          // layer2 projected features fp16
__device__ float g_as2[NN];
__device__ float g_ad2[NN];
__device__ float g_wa[9][8];
__device__ int   g_deg[NN];
__device__ int   g_col[NN * CAP];
__device__ float g_cnt[GG];

__device__ __forceinline__ float lrelu(float x) { return x > 0.f ? x : 0.2f * x; }
__device__ __forceinline__ float eluf(float x)  { return x > 0.f ? x : (__expf(x) - 1.f); }

__device__ __forceinline__ uint32_t smem_to_u32(const void* p) {
    uint32_t a;
    asm("{ .reg .u64 t; cvta.to.shared.u64 t, %1; cvt.u32.u64 %0, t; }" : "=r"(a) : "l"(p));
    return a;
}

#define LDSM_X4(r0, r1, r2, r3, addr) \
    asm volatile("ldmatrix.sync.aligned.m8n8.x4.shared.b16 {%0,%1,%2,%3}, [%4];" \
        : "=r"(r0), "=r"(r1), "=r"(r2), "=r"(r3) : "r"(addr))

__device__ __forceinline__ void mma16816h(float* d, uint32_t a0, uint32_t a1, uint32_t a2,
                                          uint32_t a3, uint32_t b0, uint32_t b1) {
    asm volatile(
        "mma.sync.aligned.m16n8k16.row.col.f32.f16.f16.f32 "
        "{%0,%1,%2,%3}, {%4,%5,%6,%7}, {%8,%9}, {%0,%1,%2,%3};"
        : "+f"(d[0]), "+f"(d[1]), "+f"(d[2]), "+f"(d[3])
        : "r"(a0), "r"(a1), "r"(a2), "r"(a3), "r"(b0), "r"(b1));
}

#define SWZC(rowIdx) (((rowIdx) & 7) << 4)

// ---------------- init: zero out / deg / cnt ----------------
__global__ void k_init(float* __restrict__ out) {
    int i = blockIdx.x * blockDim.x + threadIdx.x;
    if (i < GG * 128) out[i] = 0.f;
    if (i < NN) g_deg[i] = 0;
    if (i < GG) g_cnt[i] = 0.f;
}

// ---------------- merged: weight prep (blocks 0-328) + adjacency fill/cnt (329+) ----------------
__global__ void k_prepfill(const float* __restrict__ W1, const float* __restrict__ W2,
                           const float* __restrict__ a_src1, const float* __restrict__ a_dst1,
                           const int* __restrict__ ei, const int* __restrict__ batch) {
    int b = blockIdx.x;
    if (b < 9) {
        int gw = b * 8 + (threadIdx.x >> 5);
        int lane = threadIdx.x & 31;
        if (gw >= 72) return;
        int k = gw / 8, q = gw % 8, h = q & 3;
        const float* a = (q >= 4) ? a_dst1 : a_src1;
        float s = 0.f;
#pragma unroll
        for (int c = lane; c < 128; c += 32)
            s = fmaf(__ldg(&W1[k * 512 + h * 128 + c]), __ldg(&a[h * 128 + c]), s);
#pragma unroll
        for (int o = 16; o > 0; o >>= 1) s += __shfl_down_sync(0xffffffffu, s, o);
        if (lane == 0) g_wa[k][q] = s;
    } else if (b < 73) {
        int u = (b - 9) * 256 + threadIdx.x;
        int j = u >> 5, k = u & 31;
        __half v = __float2half(0.f);
        if (k < 27) {
            int km = k % 9;
            float w = __ldg(&W1[km * 512 + j]);
            __half hi = __float2half(w);
            v = (k < 18) ? hi : __float2half(w - __half2float(hi));
        }
        g_w1t[u] = v;
    } else if (b < 329) {
        int u = (b - 73) * 256 + threadIdx.x;
        int k = u >> 7, n = u & 127;
        g_w2t[n * 512 + k] = __float2half(__ldg(&W2[u]));
    } else {
        int i = (b - 329) * 256 + threadIdx.x;
        if (i < EE) {
            int s = ei[i], d = ei[EE + i];
            int p = atomicAdd(&g_deg[d], 1);
            if (p < CAP) g_col[d * CAP + p] = s;
        }
        if (i < NN) atomicAdd(&g_cnt[batch[i]], 1.f);
    }
}

// ---------------- as1/ad1 (thread per node) ----------------
__global__ void k_prep1(const float* __restrict__ x) {
    int n = blockIdx.x * blockDim.x + threadIdx.x;
    if (n >= NN) return;
    float xv[9];
#pragma unroll
    for (int k = 0; k < 9; k++) xv[k] = __ldg(&x[n * 9 + k]);
    float s[8];
#pragma unroll
    for (int q = 0; q < 8; q++) {
        float v = 0.f;
#pragma unroll
        for (int k = 0; k < 9; k++) v = fmaf(xv[k], g_wa[k][q], v);
        s[q] = v;
    }
    ((float4*)g_as1)[n] = make_float4(s[0], s[1], s[2], s[3]);
    ((float4*)g_ad1)[n] = make_float4(s[4], s[5], s[6], s[7]);
}

// ---------------- layer 1 aggregation over RAW x (9 dims), per head ----------------
// warp per node; lane<9 owns input dim; output: g_ax[n][h*32+k] hi/lo/hi packed.
__global__ __launch_bounds__(256) void k_agg1x(const float* __restrict__ x) {
    int n = blockIdx.x * 8 + (threadIdx.x >> 5);
    if (n >= NN) return;
    int lane = threadIdx.x & 31;
    const float4* as4 = (const float4*)g_as1;
    float4 adv = ((const float4*)g_ad1)[n];
    float4 a0 = as4[n];
    float e0 = __expf(lrelu(a0.x + adv.x));
    float e1 = __expf(lrelu(a0.y + adv.y));
    float e2 = __expf(lrelu(a0.z + adv.z));
    float e3 = __expf(lrelu(a0.w + adv.w));
    float z0 = e0, z1 = e1, z2 = e2, z3 = e3;
    float xv = (lane < 9) ? __ldg(&x[(size_t)n * 9 + lane]) : 0.f;
    float ac[4];
    ac[0] = e0 * xv; ac[1] = e1 * xv; ac[2] = e2 * xv; ac[3] = e3 * xv;
    int deg = min(g_deg[n], CAP);
    const int* col = g_col + n * CAP;
    for (int j = 0; j < deg; j++) {
        int s = col[j];
        float4 a = as4[s];
        float p0 = __expf(lrelu(a.x + adv.x));
        float p1 = __expf(lrelu(a.y + adv.y));
        float p2 = __expf(lrelu(a.z + adv.z));
        float p3 = __expf(lrelu(a.w + adv.w));
        float xs = (lane < 9) ? __ldg(&x[(size_t)s * 9 + lane]) : 0.f;
        ac[0] = fmaf(p0, xs, ac[0]);
        ac[1] = fmaf(p1, xs, ac[1]);
        ac[2] = fmaf(p2, xs, ac[2]);
        ac[3] = fmaf(p3, xs, ac[3]);
        z0 += p0; z1 += p1; z2 += p2; z3 += p3;
    }
    float iz[4];
    iz[0] = 1.f / (z0 + 1e-16f); iz[1] = 1.f / (z1 + 1e-16f);
    iz[2] = 1.f / (z2 + 1e-16f); iz[3] = 1.f / (z3 + 1e-16f);
    __half zh = __float2half(0.f);
#pragma unroll
    for (int h = 0; h < 4; h++) {
        size_t base = (size_t)n * 128 + h * 32;
        if (lane < 9) {
            float y = ac[h] * iz[h];
            __half hi = __float2half(y);
            __half lo = __float2half(y - __half2float(hi));
            g_ax[base + lane] = hi;
            g_ax[base + 9 + lane] = lo;
            g_ax[base + 18 + lane] = hi;
        } else if (lane >= 27) {
            g_ax[base + lane] = zh;
        }
    }
}

// ---------------- HMMA GEMM1b: o1 = elu(aggX @ W1T + b1); head = j-tile ----------------
// smem: A [0,16K) per-head; B [16K,32K); staging [16K,48K) overlaps B post-MMA.
__global__ __launch_bounds__(256, 2) void k_gemm1b(const float* __restrict__ b1) {
    extern __shared__ char smem[];
    char* sA = smem;
    char* sB = smem + 16384;
    char* stage = smem + 16384;
    uint32_t uA = smem_to_u32(sA);
    uint32_t uB = uA + 16384;

    int tid = threadIdx.x;
    int lane = tid & 31, wid = tid >> 5;
    int warpM = wid & 3, warpN = wid >> 2;
    int rb = warpM * 32, cb = warpN * 64;
    int m0 = blockIdx.x * 128;

    uint4 zero = make_uint4(0, 0, 0, 0);

    int g = lane >> 3;
    int aFr0 = rb + (g & 1) * 8 + (lane & 7);
    uint32_t aKb = (uint32_t)((g >> 1) << 4);
    int bFr0 = cb + (g >> 1) * 8 + (lane & 7);
    uint32_t bKb = (uint32_t)((g & 1) << 4);
    int rq = lane >> 2;
    int cq = (lane & 3) * 2;
    uint4* gdst = (uint4*)g_o1h;

    for (int jt = 0; jt < 4; jt++) {
        __syncthreads();   // staging/A reads of prev iter complete
        // load A tile (head jt): 128 rows x 4 uint4; 2 per thread
        {
#pragma unroll
            for (int it = 0; it < 2; it++) {
                int u = tid + it * 256;
                int r = u >> 2, i = u & 3;
                int row = m0 + r;
                bool ok = row < NN;
                const uint4* src = (const uint4*)(g_ax + (size_t)(ok ? row : 0) * 128 + jt * 32);
                uint32_t off = (uint32_t)(r * 128) + (((uint32_t)(i << 4)) ^ SWZC(r));
                *(uint4*)(sA + off) = ok ? src[i] : zero;
            }
        }
        // load B tile for jt
        {
#pragma unroll
            for (int it = 0; it < 2; it++) {
                int u = tid + it * 256;
                int r = u >> 2, i = u & 3;
                const uint4* src = (const uint4*)(g_w1t + (size_t)(jt * 128 + r) * 32);
                uint32_t off = (uint32_t)(r * 128) + (((uint32_t)(i << 4)) ^ SWZC(r));
                *(uint4*)(sB + off) = src[i];
            }
        }
        __syncthreads();

        float acc[2][8][4];
#pragma unroll
        for (int i = 0; i < 2; i++)
#pragma unroll
            for (int j = 0; j < 8; j++)
#pragma unroll
                for (int q = 0; q < 4; q++) acc[i][j][q] = 0.f;

#pragma unroll
        for (int kk = 0; kk < 2; kk++) {
            uint32_t kkb = (uint32_t)(kk << 5);
            uint32_t ah[2][4];
#pragma unroll
            for (int mf = 0; mf < 2; mf++) {
                int r = aFr0 + mf * 16;
                uint32_t off = (uint32_t)(r * 128) + ((kkb + aKb) ^ SWZC(r));
                LDSM_X4(ah[mf][0], ah[mf][1], ah[mf][2], ah[mf][3], uA + off);
            }
            uint32_t bh[4][4];
#pragma unroll
            for (int p = 0; p < 4; p++) {
                int r = bFr0 + p * 16;
                uint32_t off = (uint32_t)(r * 128) + ((kkb + bKb) ^ SWZC(r));
                LDSM_X4(bh[p][0], bh[p][1], bh[p][2], bh[p][3], uB + off);
            }
#pragma unroll
            for (int mf = 0; mf < 2; mf++)
#pragma unroll
                for (int p = 0; p < 4; p++) {
                    mma16816h(acc[mf][2 * p], ah[mf][0], ah[mf][1], ah[mf][2], ah[mf][3],
                              bh[p][0], bh[p][1]);
                    mma16816h(acc[mf][2 * p + 1], ah[mf][0], ah[mf][1], ah[mf][2], ah[mf][3],
                              bh[p][2], bh[p][3]);
                }
        }
        __syncthreads();   // sB reads done before staging overwrites

        // staging store with fused bias + elu (swizzled rows)
#pragma unroll
        for (int nf = 0; nf < 8; nf++) {
            int c = cb + nf * 8 + cq;
            int jg = jt * 128 + c;
            float b0v = __ldg(&b1[jg]);
            float b1v = __ldg(&b1[jg + 1]);
#pragma unroll
            for (int mf = 0; mf < 2; mf++) {
                float* a = acc[mf][nf];
                int r0 = rb + mf * 16 + rq;
                int r1 = r0 + 8;
                uint32_t o0 = r0 * 256 + (((uint32_t)(c * 2)) ^ SWZC(r0));
                uint32_t o1 = r1 * 256 + (((uint32_t)(c * 2)) ^ SWZC(r1));
                *(__half2*)(stage + o0) = __floats2half2_rn(eluf(a[0] + b0v), eluf(a[1] + b1v));
                *(__half2*)(stage + o1) = __floats2half2_rn(eluf(a[2] + b0v), eluf(a[3] + b1v));
            }
        }
        __syncthreads();

        // coalesced global copy
        {
            int jblk = jt * 16;
#pragma unroll
            for (int u = tid; u < 2048; u += 256) {
                int r = u >> 4;
                int blk = u & 15;
                uint32_t src = r * 256 + (((uint32_t)(blk << 4)) ^ SWZC(r));
                int row = m0 + r;
                if (row < NN)
                    gdst[(size_t)row * 64 + jblk + blk] = *(const uint4*)(stage + src);
            }
        }
    }
}

// ---------------- HMMA GEMM2 (sync form), swizzle-staged epilogue + fused alpha2 ----------------
__global__ __launch_bounds__(256, 2) void k_gemm2_mma(const float* __restrict__ a_src2,
                                                      const float* __restrict__ a_dst2) {
    extern __shared__ char smem[];
    char* sA = smem;
    char* sB = smem + 16384;
    uint32_t uA = smem_to_u32(sA);
    uint32_t uB = uA + 16384;

    int tid = threadIdx.x;
    int lane = tid & 31, wid = tid >> 5;
    int warpM = wid & 3, warpN = wid >> 2;
    int rb = warpM * 32, cb = warpN * 64;
    int m0 = blockIdx.x * 128;

    float acc[2][8][4];
#pragma unroll
    for (int i = 0; i < 2; i++)
#pragma unroll
        for (int j = 0; j < 8; j++)
#pragma unroll
            for (int q = 0; q < 4; q++) acc[i][j][q] = 0.f;

    int ldRow = tid >> 1;
    int ldPart = (tid & 1) * 4;
    int aRow = m0 + ldRow;
    bool aOk = aRow < NN;
    uint32_t ldSwc = SWZC(ldRow);
    uint32_t ldRowOff = ldRow * 128;

    int g = lane >> 3;
    int aFr0 = rb + (g & 1) * 8 + (lane & 7);
    uint32_t aKb = (uint32_t)((g >> 1) << 4);
    int bFr0 = cb + (g >> 1) * 8 + (lane & 7);
    uint32_t bKb = (uint32_t)((g & 1) << 4);

    for (int ch = 0; ch < 8; ch++) {
        __syncthreads();
        {
            uint4 zero = make_uint4(0, 0, 0, 0);
            const uint4* pA = (const uint4*)(g_o1h + (size_t)aRow * 512 + ch * 64);
            const uint4* pB = (const uint4*)(g_w2t + (size_t)ldRow * 512 + ch * 64);
#pragma unroll
            for (int i = 0; i < 4; i++) {
                uint32_t kb = (uint32_t)((ldPart + i) << 4);
                uint32_t off = ldRowOff + (kb ^ ldSwc);
                *(uint4*)(sA + off) = aOk ? pA[ldPart + i] : zero;
                *(uint4*)(sB + off) = pB[ldPart + i];
            }
        }
        __syncthreads();
#pragma unroll
        for (int kk = 0; kk < 4; kk++) {
            uint32_t kkb = (uint32_t)(kk << 5);
            uint32_t ah[2][4];
#pragma unroll
            for (int mf = 0; mf < 2; mf++) {
                int r = aFr0 + mf * 16;
                uint32_t off = (uint32_t)(r * 128) + ((kkb + aKb) ^ SWZC(r));
                LDSM_X4(ah[mf][0], ah[mf][1], ah[mf][2], ah[mf][3], uA + off);
            }
            uint32_t bh[4][4];
#pragma unroll
            for (int p = 0; p < 4; p++) {
                int r = bFr0 + p * 16;
                uint32_t off = (uint32_t)(r * 128) + ((kkb + bKb) ^ SWZC(r));
                LDSM_X4(bh[p][0], bh[p][1], bh[p][2], bh[p][3], uB + off);
            }
#pragma unroll
            for (int mf = 0; mf < 2; mf++)
#pragma unroll
                for (int p = 0; p < 4; p++) {
                    mma16816h(acc[mf][2 * p], ah[mf][0], ah[mf][1], ah[mf][2], ah[mf][3],
                              bh[p][0], bh[p][1]);
                    mma16816h(acc[mf][2 * p + 1], ah[mf][0], ah[mf][1], ah[mf][2], ah[mf][3],
                              bh[p][2], bh[p][3]);
                }
        }
    }

    float ps[2][2] = {{0.f, 0.f}, {0.f, 0.f}};
    float pd[2][2] = {{0.f, 0.f}, {0.f, 0.f}};
    int rq = lane >> 2;
    int cq = (lane & 3) * 2;
#pragma unroll
    for (int nf = 0; nf < 8; nf++) {
        int c = cb + nf * 8 + cq;
        float2 sv = __ldg((const float2*)(a_src2 + c));
        float2 dv = __ldg((const float2*)(a_dst2 + c));
#pragma unroll
        for (int mf = 0; mf < 2; mf++) {
            float* a = acc[mf][nf];
            ps[mf][0] = fmaf(a[0], sv.x, fmaf(a[1], sv.y, ps[mf][0]));
            ps[mf][1] = fmaf(a[2], sv.x, fmaf(a[3], sv.y, ps[mf][1]));
            pd[mf][0] = fmaf(a[0], dv.x, fmaf(a[1], dv.y, pd[mf][0]));
            pd[mf][1] = fmaf(a[2], dv.x, fmaf(a[3], dv.y, pd[mf][1]));
        }
    }

    __syncthreads();
#pragma unroll
    for (int nf = 0; nf < 8; nf++) {
        int c = cb + nf * 8 + cq;
#pragma unroll
        for (int mf = 0; mf < 2; mf++) {
            float* a = acc[mf][nf];
            int r0 = rb + mf * 16 + rq;
            int r1 = r0 + 8;
            uint32_t o0 = r0 * 256 + (((uint32_t)(c * 2)) ^ SWZC(r0));
            uint32_t o1 = r1 * 256 + (((uint32_t)(c * 2)) ^ SWZC(r1));
            *(__half2*)(smem + o0) = __floats2half2_rn(a[0], a[1]);
            *(__half2*)(smem + o1) = __floats2half2_rn(a[2], a[3]);
        }
    }
    __syncthreads();
    {
        uint4* gdst = (uint4*)g_h2h;
#pragma unroll
        for (int u = tid; u < 2048; u += 256) {
            int r = u >> 4;
            int blk = u & 15;
            uint32_t src = r * 256 + (((uint32_t)(blk << 4)) ^ SWZC(r));
            int row = m0 + r;
            if (row < NN)
                gdst[(size_t)row * 16 + blk] = *(const uint4*)(smem + src);
        }
    }
    __syncthreads();

    float* red = (float*)smem;
    if (tid < 256) red[tid] = 0.f;
    __syncthreads();
#pragma unroll
    for (int mf = 0; mf < 2; mf++)
#pragma unroll
        for (int h = 0; h < 2; h++) {
#pragma unroll
            for (int o = 1; o <= 2; o <<= 1) {
                ps[mf][h] += __shfl_xor_sync(0xffffffffu, ps[mf][h], o);
                pd[mf][h] += __shfl_xor_sync(0xffffffffu, pd[mf][h], o);
            }
        }
    if ((lane & 3) == 0) {
#pragma unroll
        for (int mf = 0; mf < 2; mf++) {
            int lr = rb + mf * 16 + rq;
            atomicAdd(&red[lr], ps[mf][0]);
            atomicAdd(&red[lr + 8], ps[mf][1]);
            atomicAdd(&red[128 + lr], pd[mf][0]);
            atomicAdd(&red[128 + lr + 8], pd[mf][1]);
        }
    }
    __syncthreads();
    if (tid < 128) {
        int row = m0 + tid;
        if (row < NN) {
            g_as2[row] = red[tid];
            g_ad2[row] = red[128 + tid];
        }
    }
}

// ---------------- layer 2 aggregation + block-merged pool atomics ----------------
__global__ __launch_bounds__(256) void k_agg2(const float* __restrict__ b2,
                                              const int* __restrict__ batch,
                                              float* __restrict__ out) {
    __shared__ float sval[8][128];
    __shared__ int sg[8];
    int w = threadIdx.x >> 5, lane = threadIdx.x & 31;
    int n = blockIdx.x * 8 + w;
    bool valid = n < NN;
    if (valid) {
        float adn = g_ad2[n];
        float e = __expf(lrelu(g_as2[n] + adn));
        float z = e;
        int deg = min(g_deg[n], CAP);
        const int* col = g_col + n * CAP;
        float a0, a1, a2, a3;
        {
            uint2 q = *(const uint2*)(g_h2h + (size_t)n * 128 + lane * 4);
            float2 f01 = __half22float2(*(__half2*)&q.x);
            float2 f23 = __half22float2(*(__half2*)&q.y);
            a0 = e * f01.x; a1 = e * f01.y; a2 = e * f23.x; a3 = e * f23.y;
        }
        for (int j = 0; j < deg; j++) {
            int s = col[j];
            float ee = __expf(lrelu(g_as2[s] + adn));
            uint2 q = *(const uint2*)(g_h2h + (size_t)s * 128 + lane * 4);
            float2 f01 = __half22float2(*(__half2*)&q.x);
            float2 f23 = __half22float2(*(__half2*)&q.y);
            a0 = fmaf(ee, f01.x, a0);
            a1 = fmaf(ee, f01.y, a1);
            a2 = fmaf(ee, f23.x, a2);
            a3 = fmaf(ee, f23.y, a3);
            z += ee;
        }
        float iz = 1.f / (z + 1e-16f);
        float4 bv = *(const float4*)(b2 + lane * 4);
        sval[w][lane * 4 + 0] = eluf(a0 * iz + bv.x);
        sval[w][lane * 4 + 1] = eluf(a1 * iz + bv.y);
        sval[w][lane * 4 + 2] = eluf(a2 * iz + bv.z);
        sval[w][lane * 4 + 3] = eluf(a3 * iz + bv.w);
        if (lane == 0) sg[w] = batch[n];
    } else if (lane == 0) {
        sg[w] = -1;
    }
    __syncthreads();
    int t = threadIdx.x;
    if (t < 128) {
        float run = 0.f;
        int curg = -1;
#pragma unroll
        for (int w2 = 0; w2 < 8; w2++) {
            int gid = sg[w2];
            if (gid < 0) continue;
            if (gid != curg) {
                if (curg >= 0) atomicAdd(&out[(size_t)curg * 128 + t], run);
                curg = gid;
                run = 0.f;
            }
            run += sval[w2][t];
        }
        if (curg >= 0) atomicAdd(&out[(size_t)curg * 128 + t], run);
    }
}

__global__ void k_pool_div(float* __restrict__ out) {
    int g = blockIdx.x, tid = threadIdx.x;
    out[g * 128 + tid] /= fmaxf(g_cnt[g], 1.f);
}

// ---------------- launcher ----------------
extern "C" void kernel_launch(void* const* d_in, const int* in_sizes, int n_in,
                              void* d_out, int out_size) {
    const float* x       = (const float*)d_in[0];
    const int*   ei      = (const int*)d_in[1];
    const int*   batch   = (const int*)d_in[2];
    const float* W1      = (const float*)d_in[3];
    const float* a_src1  = (const float*)d_in[4];
    const float* a_dst1  = (const float*)d_in[5];
    const float* b1      = (const float*)d_in[6];
    const float* W2      = (const float*)d_in[7];
    const float* a_src2  = (const float*)d_in[8];
    const float* a_dst2  = (const float*)d_in[9];
    const float* b2      = (const float*)d_in[10];
    float* out = (float*)d_out;

    cudaFuncSetAttribute(k_gemm1b, cudaFuncAttributeMaxDynamicSharedMemorySize, 49152);
    cudaFuncSetAttribute(k_gemm2_mma, cudaFuncAttributeMaxDynamicSharedMemorySize, 32768);

    k_init<<<(GG * 128 + 255) / 256, 256>>>(out);
    k_prepfill<<<329 + (EE + 255) / 256, 256>>>(W1, W2, a_src1, a_dst1, ei, batch);
    k_prep1<<<(NN + 255) / 256, 256>>>(x);
    k_agg1x<<<(NN + 7) / 8, 256>>>(x);
    k_gemm1b<<<(NN + 127) / 128, 256, 49152>>>(b1);

    k_gemm2_mma<<<(NN + 127) / 128, 256, 32768>>>(a_src2, a_dst2);

    k_agg2<<<(NN + 7) / 8, 256>>>(b2, batch, out);
    k_pool_div<<<GG, 128>>>(out);
}

// round 15
// speedup vs baseline: 1.3578x; 1.0787x over previous
#include <cuda_runtime.h>
#include <cuda_bf16.h>
#include <cuda_fp16.h>
#include <cstdint>

#define NN 100000
#define EE 300000
#define GG 4000
#define CAP 32

// ---------------- scratch (device globals; no allocation) ----------------
__device__ __align__(16) __half g_w1t[512 * 32];          // GEMM1 B: [j][W_hi(9),W_hi(9),W_lo(9),0..]
__device__ __align__(16) __half g_ax[NN * 128];           // aggregated x, per head: [n][h*32+k] hi/lo/hi
__device__ __align__(16) float g_as1[NN * 4];
__device__ __align__(16) float g_ad1[NN * 4];
__device__ __align__(16) __half g_o1h[NN * 512];          // layer1 output fp16 (GEMM2 A)
__device__ __align__(16) __half g_w2t[128 * 512];         // W2^T fp16 [n=128][k=512]
__device__ __align__(16) __half g_h2h[NN * 128];          // layer2 projected features fp16
__device__ float g_as2[NN];
__device__ float g_ad2[NN];
__device__ float g_wa[9][8];
__device__ int   g_deg[NN];
__device__ int   g_col[NN * CAP];
__device__ float g_cnt[GG];

__device__ __forceinline__ float lrelu(float x) { return x > 0.f ? x : 0.2f * x; }
__device__ __forceinline__ float eluf(float x)  { return x > 0.f ? x : (__expf(x) - 1.f); }

__device__ __forceinline__ uint32_t smem_to_u32(const void* p) {
    uint32_t a;
    asm("{ .reg .u64 t; cvta.to.shared.u64 t, %1; cvt.u32.u64 %0, t; }" : "=r"(a) : "l"(p));
    return a;
}

#define LDSM_X4(r0, r1, r2, r3, addr) \
    asm volatile("ldmatrix.sync.aligned.m8n8.x4.shared.b16 {%0,%1,%2,%3}, [%4];" \
        : "=r"(r0), "=r"(r1), "=r"(r2), "=r"(r3) : "r"(addr))

__device__ __forceinline__ void mma16816h(float* d, uint32_t a0, uint32_t a1, uint32_t a2,
                                          uint32_t a3, uint32_t b0, uint32_t b1) {
    asm volatile(
        "mma.sync.aligned.m16n8k16.row.col.f32.f16.f16.f32 "
        "{%0,%1,%2,%3}, {%4,%5,%6,%7}, {%8,%9}, {%0,%1,%2,%3};"
        : "+f"(d[0]), "+f"(d[1]), "+f"(d[2]), "+f"(d[3])
        : "r"(a0), "r"(a1), "r"(a2), "r"(a3), "r"(b0), "r"(b1));
}

#define SWZC(rowIdx) (((rowIdx) & 7) << 4)

// ---------------- init: zero out / deg / cnt ----------------
__global__ void k_init(float* __restrict__ out) {
    int i = blockIdx.x * blockDim.x + threadIdx.x;
    if (i < GG * 128) out[i] = 0.f;
    if (i < NN) g_deg[i] = 0;
    if (i < GG) g_cnt[i] = 0.f;
}

// ---------------- merged: weight prep (blocks 0-328) + adjacency fill/cnt (329+) ----------------
__global__ void k_prepfill(const float* __restrict__ W1, const float* __restrict__ W2,
                           const float* __restrict__ a_src1, const float* __restrict__ a_dst1,
                           const int* __restrict__ ei, const int* __restrict__ batch) {
    int b = blockIdx.x;
    if (b < 9) {
        int gw = b * 8 + (threadIdx.x >> 5);
        int lane = threadIdx.x & 31;
        if (gw >= 72) return;
        int k = gw / 8, q = gw % 8, h = q & 3;
        const float* a = (q >= 4) ? a_dst1 : a_src1;
        float s = 0.f;
#pragma unroll
        for (int c = lane; c < 128; c += 32)
            s = fmaf(__ldg(&W1[k * 512 + h * 128 + c]), __ldg(&a[h * 128 + c]), s);
#pragma unroll
        for (int o = 16; o > 0; o >>= 1) s += __shfl_down_sync(0xffffffffu, s, o);
        if (lane == 0) g_wa[k][q] = s;
    } else if (b < 73) {
        int u = (b - 9) * 256 + threadIdx.x;
        int j = u >> 5, k = u & 31;
        __half v = __float2half(0.f);
        if (k < 27) {
            int km = k % 9;
            float w = __ldg(&W1[km * 512 + j]);
            __half hi = __float2half(w);
            v = (k < 18) ? hi : __float2half(w - __half2float(hi));
        }
        g_w1t[u] = v;
    } else if (b < 329) {
        int u = (b - 73) * 256 + threadIdx.x;
        int k = u >> 7, n = u & 127;
        g_w2t[n * 512 + k] = __float2half(__ldg(&W2[u]));
    } else {
        int i = (b - 329) * 256 + threadIdx.x;
        if (i < EE) {
            int s = ei[i], d = ei[EE + i];
            int p = atomicAdd(&g_deg[d], 1);
            if (p < CAP) g_col[d * CAP + p] = s;
        }
        if (i < NN) atomicAdd(&g_cnt[batch[i]], 1.f);
    }
}

// ---------------- as1/ad1 (thread per node) ----------------
__global__ void k_prep1(const float* __restrict__ x) {
    int n = blockIdx.x * blockDim.x + threadIdx.x;
    if (n >= NN) return;
    float xv[9];
#pragma unroll
    for (int k = 0; k < 9; k++) xv[k] = __ldg(&x[n * 9 + k]);
    float s[8];
#pragma unroll
    for (int q = 0; q < 8; q++) {
        float v = 0.f;
#pragma unroll
        for (int k = 0; k < 9; k++) v = fmaf(xv[k], g_wa[k][q], v);
        s[q] = v;
    }
    ((float4*)g_as1)[n] = make_float4(s[0], s[1], s[2], s[3]);
    ((float4*)g_ad1)[n] = make_float4(s[4], s[5], s[6], s[7]);
}

// ---------------- layer 1 aggregation over RAW x: TWO nodes per warp (16 lanes each) ----------------
__global__ __launch_bounds__(256) void k_agg1x(const float* __restrict__ x) {
    int n = blockIdx.x * 16 + (threadIdx.x >> 4);
    int hl = threadIdx.x & 15;
    bool valid = n < NN;
    int nn = valid ? n : 0;
    const float4* as4 = (const float4*)g_as1;
    float4 adv = ((const float4*)g_ad1)[nn];
    float4 a0 = as4[nn];
    float e0 = __expf(lrelu(a0.x + adv.x));
    float e1 = __expf(lrelu(a0.y + adv.y));
    float e2 = __expf(lrelu(a0.z + adv.z));
    float e3 = __expf(lrelu(a0.w + adv.w));
    float z0 = e0, z1 = e1, z2 = e2, z3 = e3;
    float xv = (hl < 9) ? __ldg(&x[(size_t)nn * 9 + hl]) : 0.f;
    float ac[4];
    ac[0] = e0 * xv; ac[1] = e1 * xv; ac[2] = e2 * xv; ac[3] = e3 * xv;
    int deg = valid ? min(g_deg[nn], CAP) : 0;
    const int* col = g_col + (size_t)nn * CAP;
    for (int j = 0; j < deg; j++) {
        int s = col[j];
        float4 a = as4[s];
        float p0 = __expf(lrelu(a.x + adv.x));
        float p1 = __expf(lrelu(a.y + adv.y));
        float p2 = __expf(lrelu(a.z + adv.z));
        float p3 = __expf(lrelu(a.w + adv.w));
        float xs = (hl < 9) ? __ldg(&x[(size_t)s * 9 + hl]) : 0.f;
        ac[0] = fmaf(p0, xs, ac[0]);
        ac[1] = fmaf(p1, xs, ac[1]);
        ac[2] = fmaf(p2, xs, ac[2]);
        ac[3] = fmaf(p3, xs, ac[3]);
        z0 += p0; z1 += p1; z2 += p2; z3 += p3;
    }
    if (!valid) return;
    float iz[4];
    iz[0] = 1.f / (z0 + 1e-16f); iz[1] = 1.f / (z1 + 1e-16f);
    iz[2] = 1.f / (z2 + 1e-16f); iz[3] = 1.f / (z3 + 1e-16f);
    __half zh = __float2half(0.f);
#pragma unroll
    for (int h = 0; h < 4; h++) {
        size_t base = (size_t)n * 128 + h * 32;
        if (hl < 9) {
            float y = ac[h] * iz[h];
            __half hi = __float2half(y);
            __half lo = __float2half(y - __half2float(hi));
            g_ax[base + hl] = hi;
            g_ax[base + 9 + hl] = lo;
            g_ax[base + 18 + hl] = hi;
        } else if (hl >= 11) {
            g_ax[base + 16 + hl] = zh;   // slots 27..31
        }
    }
}

// ---------------- HMMA GEMM1b: o1 = elu(aggX @ W1T + b1); head = j-tile ----------------
__global__ __launch_bounds__(256, 2) void k_gemm1b(const float* __restrict__ b1) {
    extern __shared__ char smem[];
    char* sA = smem;
    char* sB = smem + 16384;
    char* stage = smem + 16384;
    uint32_t uA = smem_to_u32(sA);
    uint32_t uB = uA + 16384;

    int tid = threadIdx.x;
    int lane = tid & 31, wid = tid >> 5;
    int warpM = wid & 3, warpN = wid >> 2;
    int rb = warpM * 32, cb = warpN * 64;
    int m0 = blockIdx.x * 128;

    uint4 zero = make_uint4(0, 0, 0, 0);

    int g = lane >> 3;
    int aFr0 = rb + (g & 1) * 8 + (lane & 7);
    uint32_t aKb = (uint32_t)((g >> 1) << 4);
    int bFr0 = cb + (g >> 1) * 8 + (lane & 7);
    uint32_t bKb = (uint32_t)((g & 1) << 4);
    int rq = lane >> 2;
    int cq = (lane & 3) * 2;
    uint4* gdst = (uint4*)g_o1h;

    for (int jt = 0; jt < 4; jt++) {
        __syncthreads();
        {
#pragma unroll
            for (int it = 0; it < 2; it++) {
                int u = tid + it * 256;
                int r = u >> 2, i = u & 3;
                int row = m0 + r;
                bool ok = row < NN;
                const uint4* src = (const uint4*)(g_ax + (size_t)(ok ? row : 0) * 128 + jt * 32);
                uint32_t off = (uint32_t)(r * 128) + (((uint32_t)(i << 4)) ^ SWZC(r));
                *(uint4*)(sA + off) = ok ? src[i] : zero;
            }
        }
        {
#pragma unroll
            for (int it = 0; it < 2; it++) {
                int u = tid + it * 256;
                int r = u >> 2, i = u & 3;
                const uint4* src = (const uint4*)(g_w1t + (size_t)(jt * 128 + r) * 32);
                uint32_t off = (uint32_t)(r * 128) + (((uint32_t)(i << 4)) ^ SWZC(r));
                *(uint4*)(sB + off) = src[i];
            }
        }
        __syncthreads();

        float acc[2][8][4];
#pragma unroll
        for (int i = 0; i < 2; i++)
#pragma unroll
            for (int j = 0; j < 8; j++)
#pragma unroll
                for (int q = 0; q < 4; q++) acc[i][j][q] = 0.f;

#pragma unroll
        for (int kk = 0; kk < 2; kk++) {
            uint32_t kkb = (uint32_t)(kk << 5);
            uint32_t ah[2][4];
#pragma unroll
            for (int mf = 0; mf < 2; mf++) {
                int r = aFr0 + mf * 16;
                uint32_t off = (uint32_t)(r * 128) + ((kkb + aKb) ^ SWZC(r));
                LDSM_X4(ah[mf][0], ah[mf][1], ah[mf][2], ah[mf][3], uA + off);
            }
            uint32_t bh[4][4];
#pragma unroll
            for (int p = 0; p < 4; p++) {
                int r = bFr0 + p * 16;
                uint32_t off = (uint32_t)(r * 128) + ((kkb + bKb) ^ SWZC(r));
                LDSM_X4(bh[p][0], bh[p][1], bh[p][2], bh[p][3], uB + off);
            }
#pragma unroll
            for (int mf = 0; mf < 2; mf++)
#pragma unroll
                for (int p = 0; p < 4; p++) {
                    mma16816h(acc[mf][2 * p], ah[mf][0], ah[mf][1], ah[mf][2], ah[mf][3],
                              bh[p][0], bh[p][1]);
                    mma16816h(acc[mf][2 * p + 1], ah[mf][0], ah[mf][1], ah[mf][2], ah[mf][3],
                              bh[p][2], bh[p][3]);
                }
        }
        __syncthreads();

#pragma unroll
        for (int nf = 0; nf < 8; nf++) {
            int c = cb + nf * 8 + cq;
            int jg = jt * 128 + c;
            float b0v = __ldg(&b1[jg]);
            float b1v = __ldg(&b1[jg + 1]);
#pragma unroll
            for (int mf = 0; mf < 2; mf++) {
                float* a = acc[mf][nf];
                int r0 = rb + mf * 16 + rq;
                int r1 = r0 + 8;
                uint32_t o0 = r0 * 256 + (((uint32_t)(c * 2)) ^ SWZC(r0));
                uint32_t o1 = r1 * 256 + (((uint32_t)(c * 2)) ^ SWZC(r1));
                *(__half2*)(stage + o0) = __floats2half2_rn(eluf(a[0] + b0v), eluf(a[1] + b1v));
                *(__half2*)(stage + o1) = __floats2half2_rn(eluf(a[2] + b0v), eluf(a[3] + b1v));
            }
        }
        __syncthreads();

        {
            int jblk = jt * 16;
#pragma unroll
            for (int u = tid; u < 2048; u += 256) {
                int r = u >> 4;
                int blk = u & 15;
                uint32_t src = r * 256 + (((uint32_t)(blk << 4)) ^ SWZC(r));
                int row = m0 + r;
                if (row < NN)
                    gdst[(size_t)row * 64 + jblk + blk] = *(const uint4*)(stage + src);
            }
        }
    }
}

// ---------------- HMMA GEMM2 (sync form), swizzle-staged epilogue + fused alpha2 ----------------
__global__ __launch_bounds__(256, 2) void k_gemm2_mma(const float* __restrict__ a_src2,
                                                      const float* __restrict__ a_dst2) {
    extern __shared__ char smem[];
    char* sA = smem;
    char* sB = smem + 16384;
    uint32_t uA = smem_to_u32(sA);
    uint32_t uB = uA + 16384;

    int tid = threadIdx.x;
    int lane = tid & 31, wid = tid >> 5;
    int warpM = wid & 3, warpN = wid >> 2;
    int rb = warpM * 32, cb = warpN * 64;
    int m0 = blockIdx.x * 128;

    float acc[2][8][4];
#pragma unroll
    for (int i = 0; i < 2; i++)
#pragma unroll
        for (int j = 0; j < 8; j++)
#pragma unroll
            for (int q = 0; q < 4; q++) acc[i][j][q] = 0.f;

    int ldRow = tid >> 1;
    int ldPart = (tid & 1) * 4;
    int aRow = m0 + ldRow;
    bool aOk = aRow < NN;
    uint32_t ldSwc = SWZC(ldRow);
    uint32_t ldRowOff = ldRow * 128;

    int g = lane >> 3;
    int aFr0 = rb + (g & 1) * 8 + (lane & 7);
    uint32_t aKb = (uint32_t)((g >> 1) << 4);
    int bFr0 = cb + (g >> 1) * 8 + (lane & 7);
    uint32_t bKb = (uint32_t)((g & 1) << 4);

    for (int ch = 0; ch < 8; ch++) {
        __syncthreads();
        {
            uint4 zero = make_uint4(0, 0, 0, 0);
            const uint4* pA = (const uint4*)(g_o1h + (size_t)aRow * 512 + ch * 64);
            const uint4* pB = (const uint4*)(g_w2t + (size_t)ldRow * 512 + ch * 64);
#pragma unroll
            for (int i = 0; i < 4; i++) {
                uint32_t kb = (uint32_t)((ldPart + i) << 4);
                uint32_t off = ldRowOff + (kb ^ ldSwc);
                *(uint4*)(sA + off) = aOk ? pA[ldPart + i] : zero;
                *(uint4*)(sB + off) = pB[ldPart + i];
            }
        }
        __syncthreads();
#pragma unroll
        for (int kk = 0; kk < 4; kk++) {
            uint32_t kkb = (uint32_t)(kk << 5);
            uint32_t ah[2][4];
#pragma unroll
            for (int mf = 0; mf < 2; mf++) {
                int r = aFr0 + mf * 16;
                uint32_t off = (uint32_t)(r * 128) + ((kkb + aKb) ^ SWZC(r));
                LDSM_X4(ah[mf][0], ah[mf][1], ah[mf][2], ah[mf][3], uA + off);
            }
            uint32_t bh[4][4];
#pragma unroll
            for (int p = 0; p < 4; p++) {
                int r = bFr0 + p * 16;
                uint32_t off = (uint32_t)(r * 128) + ((kkb + bKb) ^ SWZC(r));
                LDSM_X4(bh[p][0], bh[p][1], bh[p][2], bh[p][3], uB + off);
            }
#pragma unroll
            for (int mf = 0; mf < 2; mf++)
#pragma unroll
                for (int p = 0; p < 4; p++) {
                    mma16816h(acc[mf][2 * p], ah[mf][0], ah[mf][1], ah[mf][2], ah[mf][3],
                              bh[p][0], bh[p][1]);
                    mma16816h(acc[mf][2 * p + 1], ah[mf][0], ah[mf][1], ah[mf][2], ah[mf][3],
                              bh[p][2], bh[p][3]);
                }
        }
    }

    float ps[2][2] = {{0.f, 0.f}, {0.f, 0.f}};
    float pd[2][2] = {{0.f, 0.f}, {0.f, 0.f}};
    int rq = lane >> 2;
    int cq = (lane & 3) * 2;
#pragma unroll
    for (int nf = 0; nf < 8; nf++) {
        int c = cb + nf * 8 + cq;
        float2 sv = __ldg((const float2*)(a_src2 + c));
        float2 dv = __ldg((const float2*)(a_dst2 + c));
#pragma unroll
        for (int mf = 0; mf < 2; mf++) {
            float* a = acc[mf][nf];
            ps[mf][0] = fmaf(a[0], sv.x, fmaf(a[1], sv.y, ps[mf][0]));
            ps[mf][1] = fmaf(a[2], sv.x, fmaf(a[3], sv.y, ps[mf][1]));
            pd[mf][0] = fmaf(a[0], dv.x, fmaf(a[1], dv.y, pd[mf][0]));
            pd[mf][1] = fmaf(a[2], dv.x, fmaf(a[3], dv.y, pd[mf][1]));
        }
    }

    __syncthreads();
#pragma unroll
    for (int nf = 0; nf < 8; nf++) {
        int c = cb + nf * 8 + cq;
#pragma unroll
        for (int mf = 0; mf < 2; mf++) {
            float* a = acc[mf][nf];
            int r0 = rb + mf * 16 + rq;
            int r1 = r0 + 8;
            uint32_t o0 = r0 * 256 + (((uint32_t)(c * 2)) ^ SWZC(r0));
            uint32_t o1 = r1 * 256 + (((uint32_t)(c * 2)) ^ SWZC(r1));
            *(__half2*)(smem + o0) = __floats2half2_rn(a[0], a[1]);
            *(__half2*)(smem + o1) = __floats2half2_rn(a[2], a[3]);
        }
    }
    __syncthreads();
    {
        uint4* gdst = (uint4*)g_h2h;
#pragma unroll
        for (int u = tid; u < 2048; u += 256) {
            int r = u >> 4;
            int blk = u & 15;
            uint32_t src = r * 256 + (((uint32_t)(blk << 4)) ^ SWZC(r));
            int row = m0 + r;
            if (row < NN)
                gdst[(size_t)row * 16 + blk] = *(const uint4*)(smem + src);
        }
    }
    __syncthreads();

    float* red = (float*)smem;
    if (tid < 256) red[tid] = 0.f;
    __syncthreads();
#pragma unroll
    for (int mf = 0; mf < 2; mf++)
#pragma unroll
        for (int h = 0; h < 2; h++) {
#pragma unroll
            for (int o = 1; o <= 2; o <<= 1) {
                ps[mf][h] += __shfl_xor_sync(0xffffffffu, ps[mf][h], o);
                pd[mf][h] += __shfl_xor_sync(0xffffffffu, pd[mf][h], o);
            }
        }
    if ((lane & 3) == 0) {
#pragma unroll
        for (int mf = 0; mf < 2; mf++) {
            int lr = rb + mf * 16 + rq;
            atomicAdd(&red[lr], ps[mf][0]);
            atomicAdd(&red[lr + 8], ps[mf][1]);
            atomicAdd(&red[128 + lr], pd[mf][0]);
            atomicAdd(&red[128 + lr + 8], pd[mf][1]);
        }
    }
    __syncthreads();
    if (tid < 128) {
        int row = m0 + tid;
        if (row < NN) {
            g_as2[row] = red[tid];
            g_ad2[row] = red[128 + tid];
        }
    }
}

// ---------------- layer 2 aggregation + block-merged pool atomics ----------------
__global__ __launch_bounds__(256) void k_agg2(const float* __restrict__ b2,
                                              const int* __restrict__ batch,
                                              float* __restrict__ out) {
    __shared__ float sval[8][128];
    __shared__ int sg[8];
    int w = threadIdx.x >> 5, lane = threadIdx.x & 31;
    int n = blockIdx.x * 8 + w;
    bool valid = n < NN;
    if (valid) {
        float adn = g_ad2[n];
        float e = __expf(lrelu(g_as2[n] + adn));
        float z = e;
        int deg = min(g_deg[n], CAP);
        const int* col = g_col + n * CAP;
        float a0, a1, a2, a3;
        {
            uint2 q = *(const uint2*)(g_h2h + (size_t)n * 128 + lane * 4);
            float2 f01 = __half22float2(*(__half2*)&q.x);
            float2 f23 = __half22float2(*(__half2*)&q.y);
            a0 = e * f01.x; a1 = e * f01.y; a2 = e * f23.x; a3 = e * f23.y;
        }
        for (int j = 0; j < deg; j++) {
            int s = col[j];
            float ee = __expf(lrelu(g_as2[s] + adn));
            uint2 q = *(const uint2*)(g_h2h + (size_t)s * 128 + lane * 4);
            float2 f01 = __half22float2(*(__half2*)&q.x);
            float2 f23 = __half22float2(*(__half2*)&q.y);
            a0 = fmaf(ee, f01.x, a0);
            a1 = fmaf(ee, f01.y, a1);
            a2 = fmaf(ee, f23.x, a2);
            a3 = fmaf(ee, f23.y, a3);
            z += ee;
        }
        float iz = 1.f / (z + 1e-16f);
        float4 bv = *(const float4*)(b2 + lane * 4);
        sval[w][lane * 4 + 0] = eluf(a0 * iz + bv.x);
        sval[w][lane * 4 + 1] = eluf(a1 * iz + bv.y);
        sval[w][lane * 4 + 2] = eluf(a2 * iz + bv.z);
        sval[w][lane * 4 + 3] = eluf(a3 * iz + bv.w);
        if (lane == 0) sg[w] = batch[n];
    } else if (lane == 0) {
        sg[w] = -1;
    }
    __syncthreads();
    int t = threadIdx.x;
    if (t < 128) {
        float run = 0.f;
        int curg = -1;
#pragma unroll
        for (int w2 = 0; w2 < 8; w2++) {
            int gid = sg[w2];
            if (gid < 0) continue;
            if (gid != curg) {
                if (curg >= 0) atomicAdd(&out[(size_t)curg * 128 + t], run);
                curg = gid;
                run = 0.f;
            }
            run += sval[w2][t];
        }
        if (curg >= 0) atomicAdd(&out[(size_t)curg * 128 + t], run);
    }
}

__global__ void k_pool_div(float* __restrict__ out) {
    int g = blockIdx.x, tid = threadIdx.x;
    out[g * 128 + tid] /= fmaxf(g_cnt[g], 1.f);
}

// ---------------- launcher ----------------
extern "C" void kernel_launch(void* const* d_in, const int* in_sizes, int n_in,
                              void* d_out, int out_size) {
    const float* x       = (const float*)d_in[0];
    const int*   ei      = (const int*)d_in[1];
    const int*   batch   = (const int*)d_in[2];
    const float* W1      = (const float*)d_in[3];
    const float* a_src1  = (const float*)d_in[4];
    const float* a_dst1  = (const float*)d_in[5];
    const float* b1      = (const float*)d_in[6];
    const float* W2      = (const float*)d_in[7];
    const float* a_src2  = (const float*)d_in[8];
    const float* a_dst2  = (const float*)d_in[9];
    const float* b2      = (const float*)d_in[10];
    float* out = (float*)d_out;

    cudaFuncSetAttribute(k_gemm1b, cudaFuncAttributeMaxDynamicSharedMemorySize, 49152);
    cudaFuncSetAttribute(k_gemm2_mma, cudaFuncAttributeMaxDynamicSharedMemorySize, 32768);

    k_init<<<(GG * 128 + 255) / 256, 256>>>(out);
    k_prepfill<<<329 + (EE + 255) / 256, 256>>>(W1, W2, a_src1, a_dst1, ei, batch);
    k_prep1<<<(NN + 255) / 256, 256>>>(x);
    k_agg1x<<<(NN + 15) / 16, 256>>>(x);
    k_gemm1b<<<(NN + 127) / 128, 256, 49152>>>(b1);

    k_gemm2_mma<<<(NN + 127) / 128, 256, 32768>>>(a_src2, a_dst2);

    k_agg2<<<(NN + 7) / 8, 256>>>(b2, batch, out);
    k_pool_div<<<GG, 128>>>(out);
}